// round 13
// baseline (speedup 1.0000x reference)
#include <cuda_runtime.h>
#include <cuda_fp16.h>
#include <cstdint>

#define BATCH 16
#define DIM 256
#define HH 56
#define WW 56
#define HWX (HH*WW)          // 3136
#define HEADS 8
#define DH 32
#define HP1 28
#define HW1 (HP1*HP1)        // 784
#define HP2 14
#define HWP (HP2*HP2)        // 196
#define BN_EPS 1e-5f

#define SW128(x) ((x) ^ (((x) >> 3) & 0x70))

typedef __half fp16;

__device__ __forceinline__ uint32_t smem_u32(const void* p) {
  uint32_t a;
  asm("{ .reg .u64 t; cvta.to.shared.u64 t, %1; cvt.u32.u64 %0, t; }" : "=r"(a) : "l"(p));
  return a;
}
__device__ __forceinline__ void ldm4(uint32_t a[4], uint32_t addr) {
  asm volatile("ldmatrix.sync.aligned.m8n8.x4.shared.b16 {%0,%1,%2,%3}, [%4];"
               : "=r"(a[0]), "=r"(a[1]), "=r"(a[2]), "=r"(a[3]) : "r"(addr));
}
__device__ __forceinline__ void ldm4t(uint32_t a[4], uint32_t addr) {
  asm volatile("ldmatrix.sync.aligned.m8n8.x4.trans.shared.b16 {%0,%1,%2,%3}, [%4];"
               : "=r"(a[0]), "=r"(a[1]), "=r"(a[2]), "=r"(a[3]) : "r"(addr));
}
__device__ __forceinline__ void mmaF32(float d[4], const uint32_t a[4], const uint32_t b[2]) {
  asm volatile("mma.sync.aligned.m16n8k16.row.col.f32.f16.f16.f32 "
               "{%0,%1,%2,%3}, {%4,%5,%6,%7}, {%8,%9}, {%0,%1,%2,%3};"
               : "+f"(d[0]), "+f"(d[1]), "+f"(d[2]), "+f"(d[3])
               : "r"(a[0]), "r"(a[1]), "r"(a[2]), "r"(a[3]), "r"(b[0]), "r"(b[1]));
}
__device__ __forceinline__ void mmaF16(uint32_t d[2], const uint32_t a[4], const uint32_t b[2]) {
  asm volatile("mma.sync.aligned.m16n8k16.row.col.f16.f16.f16.f16 "
               "{%0,%1}, {%2,%3,%4,%5}, {%6,%7}, {%0,%1};"
               : "+r"(d[0]), "+r"(d[1])
               : "r"(a[0]), "r"(a[1]), "r"(a[2]), "r"(a[3]), "r"(b[0]), "r"(b[1]));
}
__device__ __forceinline__ uint32_t hpack(float a, float b) {
  __half2 t = __floats2half2_rn(a, b);
  return *(uint32_t*)&t;
}
__device__ __forceinline__ float hlo(uint32_t v) { return __half2float(((__half2*)&v)->x); }
__device__ __forceinline__ float hhi(uint32_t v) { return __half2float(((__half2*)&v)->y); }

// ---------------- scratch (device globals; no allocations allowed) ----------------
#define NX (BATCH*DIM*HWX)
#define NP0 (BATCH*DIM*HW1)
#define NPF (BATCH*DIM*HWP)
#define NKV (BATCH*2*DIM*HWP)
#define WOFF_Q 0
#define WOFF_PL 65536
#define WOFF_KV 131072
#define WOFF_MIX 262144
#define NW 327680
__device__ fp16 g_xh[NX];
__device__ fp16 g_qh[NX];
__device__ fp16 g_mh[NX];
__device__ fp16 g_gf16[NX];
__device__ fp16 g_p0h[NP0];
__device__ fp16 g_pm16[NP0];
__device__ fp16 g_pfh[NPF];
__device__ fp16 g_kvh[NKV], g_kvl[NKV];
__device__ fp16 g_wh[NW],  g_wl[NW];

// ---------------- x -> fp16 hi ----------------
__global__ __launch_bounds__(256) void cvt_h_kernel(
    const float* __restrict__ s, fp16* __restrict__ h, int n4) {
  int i = blockIdx.x * 256 + threadIdx.x;
  if (i >= n4) return;
  float4 v = ((const float4*)s)[i];
  ((__half2*)h)[2*i]   = __floats2half2_rn(v.x, v.y);
  ((__half2*)h)[2*i+1] = __floats2half2_rn(v.z, v.w);
}
// ---------------- fused weight hi/lo split ----------------
__global__ __launch_bounds__(256) void cvt_w_kernel(
    const float* __restrict__ qw, const float* __restrict__ plw,
    const float* __restrict__ kvw, const float* __restrict__ mxw,
    fp16* __restrict__ h, fp16* __restrict__ l) {
  int i = blockIdx.x * 256 + threadIdx.x;
  if (i >= NW / 4) return;
  const float* src;
  int li;
  if (i < 16384)      { src = qw;  li = i; }
  else if (i < 32768) { src = plw; li = i - 16384; }
  else if (i < 65536) { src = kvw; li = i - 32768; }
  else                { src = mxw; li = i - 65536; }
  float4 v = ((const float4*)src)[li];
  __half2 h0 = __floats2half2_rn(v.x, v.y);
  __half2 h1 = __floats2half2_rn(v.z, v.w);
  __half2 l0 = __floats2half2_rn(v.x - __half2float(h0.x), v.y - __half2float(h0.y));
  __half2 l1 = __floats2half2_rn(v.z - __half2float(h1.x), v.w - __half2float(h1.y));
  ((__half2*)h)[2*i] = h0; ((__half2*)h)[2*i+1] = h1;
  ((__half2*)l)[2*i] = l0; ((__half2*)l)[2*i+1] = l1;
}

// ---------------- 1x1 conv: 2-pass split-fp16 HMMA, x4-trans B loads ----------------
#define CV_SMEM 49152

__global__ __launch_bounds__(256) void conv1x1_hf_kernel(
    const fp16* __restrict__ Ah, const fp16* __restrict__ Al,
    const fp16* __restrict__ Bh,
    const float* __restrict__ bias, float* __restrict__ Yf,
    fp16* __restrict__ Yh, fp16* __restrict__ Yl,
    int CO, int CI, int HW) {
  extern __shared__ __align__(1024) char smem[];
  char* sAh = smem;         char* sAl = smem + 16384;
  char* sBh = smem + 32768;
  uint32_t aAh = smem_u32(sAh), aAl = smem_u32(sAl);
  uint32_t aBh = smem_u32(sBh);
  int tid = threadIdx.x, lane = tid & 31, wid = tid >> 5;
  int m0 = blockIdx.y * 128, n0 = blockIdx.x * 128;
  const fp16* Bhb = Bh + (size_t)blockIdx.z * CI * HW;
  int mw = (wid & 3) * 32, nw = (wid >> 2) * 64;

  float acc[2][8][4];
  uint32_t accH[2][8][2];
#pragma unroll
  for (int i = 0; i < 2; i++)
#pragma unroll
    for (int j = 0; j < 8; j++) {
#pragma unroll
      for (int c = 0; c < 4; c++) acc[i][j][c] = 0.f;
      accH[i][j][0] = 0u; accH[i][j][1] = 0u;
    }

  for (int k0 = 0; k0 < CI; k0 += 64) {
#pragma unroll
    for (int i = 0; i < 4; i++) {
      int t = tid + i * 256;
      int m = t >> 3, kg = t & 7;
      size_t src = (size_t)(m0 + m) * CI + k0 + kg * 8;
      uint32_t dst = SW128(m * 128 + kg * 16);
      *(uint4*)(sAh + dst) = *(const uint4*)(Ah + src);
      *(uint4*)(sAl + dst) = *(const uint4*)(Al + src);
    }
#pragma unroll
    for (int i = 0; i < 4; i++) {
      int t = tid + i * 256;
      int k = t & 63, c = t >> 6;
      int gn = n0 + c * 8;
      uint4 vh;
      if (gn + 8 <= HW) {
        const char* ph = (const char*)(Bhb + (size_t)(k0 + k) * HW + gn);
        uint2 h0 = *(const uint2*)ph, h1 = *(const uint2*)(ph + 8);
        vh = make_uint4(h0.x, h0.y, h1.x, h1.y);
      } else {
        fp16 th[8];
#pragma unroll
        for (int j = 0; j < 8; j++) {
          int g = gn + j;
          th[j] = (g < HW) ? Bhb[(size_t)(k0 + k) * HW + g] : __float2half(0.f);
        }
        vh = *(uint4*)th;
      }
      *(uint4*)(sBh + (k * 256 + ((c ^ (k & 15)) << 4))) = vh;
    }
    __syncthreads();
#pragma unroll
    for (int s = 0; s < 4; s++) {
      uint32_t ah[2][4], al[2][4];
#pragma unroll
      for (int tm = 0; tm < 2; tm++) {
        uint32_t off = SW128((mw + tm * 16 + (lane & 15)) * 128 + s * 32 + (lane >> 4) * 16);
        ldm4(ah[tm], aAh + off);
        ldm4(al[tm], aAl + off);
      }
      int kk = s * 16 + (lane & 15);
#pragma unroll
      for (int ntp = 0; ntp < 4; ntp++) {
        int nt_eff = 2 * ntp + (lane >> 4);
        uint32_t cIdx = (uint32_t)(((nw >> 3) + nt_eff) ^ (kk & 15));
        uint32_t bq[4];
        ldm4t(bq, aBh + kk * 256 + (cIdx << 4));
#pragma unroll
        for (int tm = 0; tm < 2; tm++) {
          mmaF32(acc[tm][2*ntp],   ah[tm], bq);
          mmaF16(accH[tm][2*ntp],  al[tm], bq);
          mmaF32(acc[tm][2*ntp+1], ah[tm], bq + 2);
          mmaF16(accH[tm][2*ntp+1],al[tm], bq + 2);
        }
      }
    }
    __syncthreads();
  }
#pragma unroll
  for (int tm = 0; tm < 2; tm++) {
    int r0 = m0 + mw + tm * 16 + (lane >> 2);
    float b0 = bias[r0], b1 = bias[r0 + 8];
#pragma unroll
    for (int tn = 0; tn < 8; tn++) {
      int col = n0 + nw + tn * 8 + (lane & 3) * 2;
      if (col < HW) {
        float o0 = acc[tm][tn][0] + hlo(accH[tm][tn][0]) + b0;
        float o1 = acc[tm][tn][1] + hhi(accH[tm][tn][0]) + b0;
        float o2 = acc[tm][tn][2] + hlo(accH[tm][tn][1]) + b1;
        float o3 = acc[tm][tn][3] + hhi(accH[tm][tn][1]) + b1;
        size_t i0 = (size_t)blockIdx.z * CO * HW + (size_t)r0 * HW + col;
        size_t i1 = i0 + (size_t)8 * HW;
        if (Yf) {
          *(float2*)&Yf[i0] = make_float2(o0, o1);
          *(float2*)&Yf[i1] = make_float2(o2, o3);
        }
        if (Yh) {
          __half2 h0 = __floats2half2_rn(o0, o1);
          __half2 h1 = __floats2half2_rn(o2, o3);
          *(__half2*)&Yh[i0] = h0; *(__half2*)&Yh[i1] = h1;
          if (Yl) {
            __half2 l0 = __floats2half2_rn(o0 - __half2float(h0.x), o1 - __half2float(h0.y));
            __half2 l1 = __floats2half2_rn(o2 - __half2float(h1.x), o3 - __half2float(h1.y));
            *(__half2*)&Yl[i0] = l0; *(__half2*)&Yl[i1] = l1;
          }
        }
      }
    }
  }
}

// ---------------- dw1: 5x5 s2 + BN, fp32 x -> fp16, smem-tiled, block per (b,c) -------
// padded tile: 60 rows x 64 cols f32, interior at (+2, +4); aligned float4 stores.
__global__ __launch_bounds__(256) void dw1_tiled_kernel(
    const float* __restrict__ X, const float* __restrict__ Wd,
    const float* __restrict__ bias, const float* __restrict__ gam,
    const float* __restrict__ bet, const float* __restrict__ mu,
    const float* __restrict__ var, fp16* __restrict__ Yh) {
  __shared__ float sp[60 * 64];
  int tid = threadIdx.x;
  int bc = blockIdx.x;
  int c = bc & (DIM - 1);
  for (int i = tid; i < 60 * 64 / 4; i += 256) ((float4*)sp)[i] = make_float4(0, 0, 0, 0);
  __syncthreads();
  const float* xp = X + (size_t)bc * HWX;
  for (int i = tid; i < HWX / 4; i += 256) {      // 784 float4
    float4 v = ((const float4*)xp)[i];
    int e = i * 4, r = e / WW, col = e - r * WW;  // WW%4==0 -> same row, aligned
    *(float4*)&sp[(r + 2) * 64 + col + 4] = v;
  }
  float w[25];
#pragma unroll
  for (int j = 0; j < 25; j++) w[j] = Wd[c * 25 + j];
  float bsv = bias[c];
  float sc = gam[c] * rsqrtf(var[c] + BN_EPS);
  float muv = mu[c], bev = bet[c];
  __syncthreads();
  fp16* yp = Yh + (size_t)bc * HW1;
  for (int o = tid; o < HW1; o += 256) {
    int oy = o / HP1, ox = o - oy * HP1;
    float s = 0.f;
#pragma unroll
    for (int ky = 0; ky < 5; ky++) {
      const float* row = &sp[(oy * 2 + ky) * 64 + ox * 2 + 2];
#pragma unroll
      for (int kx = 0; kx < 5; kx++) s += row[kx] * w[ky * 5 + kx];
    }
    yp[o] = __float2half_rn((s + bsv - muv) * sc + bev);
  }
}

// ---------------- dw2: 5x5 s2 + BN, fp16 -> fp16, smem-tiled, block per (b,c) --------
// padded tile: 32 rows x 32 cols fp16, interior at (+2, +2).
__global__ __launch_bounds__(256) void dw2_tiled_kernel(
    const fp16* __restrict__ X, const float* __restrict__ Wd,
    const float* __restrict__ bias, const float* __restrict__ gam,
    const float* __restrict__ bet, const float* __restrict__ mu,
    const float* __restrict__ var, fp16* __restrict__ Yh) {
  __shared__ fp16 sp[32 * 32];
  int tid = threadIdx.x;
  int bc = blockIdx.x;
  int c = bc & (DIM - 1);
  for (int i = tid; i < 32 * 32 / 2; i += 256) ((__half2*)sp)[i] = __floats2half2_rn(0, 0);
  __syncthreads();
  const fp16* xp = X + (size_t)bc * HW1;
  for (int i = tid; i < HW1 / 2; i += 256) {       // 392 half2
    __half2 v = ((const __half2*)xp)[i];
    int e = i * 2, r = e / HP1, col = e - r * HP1; // HP1 even -> same row, h2-aligned
    *(__half2*)&sp[(r + 2) * 32 + col + 2] = v;
  }
  float w[25];
#pragma unroll
  for (int j = 0; j < 25; j++) w[j] = Wd[c * 25 + j];
  float bsv = bias[c];
  float sc = gam[c] * rsqrtf(var[c] + BN_EPS);
  float muv = mu[c], bev = bet[c];
  __syncthreads();
  fp16* yp = Yh + (size_t)bc * HWP;
  if (tid < HWP) {
    int oy = tid / HP2, ox = tid - oy * HP2;
    float s = 0.f;
#pragma unroll
    for (int ky = 0; ky < 5; ky++) {
      const fp16* row = &sp[(oy * 2 + ky) * 32 + ox * 2];
#pragma unroll
      for (int kx = 0; kx < 5; kx++) s += __half2float(row[kx]) * w[ky * 5 + kx];
    }
    yp[tid] = __float2half_rn((s + bsv - muv) * sc + bev);
  }
}

// ---------------- gate: dw5x5 s1 + SiLU + sigmoid-gate, smem-tiled, block per (b,c) ---
// padded q tile: 60 rows x 72 cols fp16, interior at (+2, +8); gf/out direct gmem.
__global__ __launch_bounds__(256) void gate_tiled_kernel(
    const fp16* __restrict__ Q, const float* __restrict__ Wd,
    const float* __restrict__ bias, const fp16* __restrict__ G,
    fp16* __restrict__ Oh) {
  __shared__ fp16 sp[60 * 72];
  int tid = threadIdx.x;
  int bc = blockIdx.x;
  int c = bc & (DIM - 1);
  for (int i = tid; i < 60 * 72 / 8; i += 256)
    ((uint4*)sp)[i] = make_uint4(0, 0, 0, 0);
  __syncthreads();
  const fp16* qp = Q + (size_t)bc * HWX;
  for (int i = tid; i < HWX / 8; i += 256) {       // 392 uint4
    uint4 v = ((const uint4*)qp)[i];
    int e = i * 8, r = e / WW, col = e - r * WW;   // WW%8==0 -> same row, aligned
    *(uint4*)&sp[(r + 2) * 72 + col + 8] = v;
  }
  float w[25];
#pragma unroll
  for (int j = 0; j < 25; j++) w[j] = Wd[c * 25 + j];
  float bsv = bias[c];
  __syncthreads();
  const fp16* gp = G + (size_t)bc * HWX;
  fp16* op = Oh + (size_t)bc * HWX;
  for (int o = tid; o < HWX; o += 256) {
    int oy = o / WW, ox = o - oy * WW;
    float s = 0.f;
#pragma unroll
    for (int ky = 0; ky < 5; ky++) {
      const fp16* row = &sp[(oy + ky) * 72 + ox + 6];
#pragma unroll
      for (int kx = 0; kx < 5; kx++) s += __half2float(row[kx]) * w[ky * 5 + kx];
    }
    s += bsv;
    float lf = s / (1.f + __expf(-s));
    float gv = __half2float(gp[o]);
    float sg = 1.f / (1.f + __expf(-gv));
    op[o] = __float2half_rn(lf * sg * gv);
  }
}

// ---------------- attention v7: x4 B-loads, no max-pass, fp16 output ----------------
#define A6_AQH 0
#define A6_KH  8704
#define A6_KL  26624
#define A6_VH  44544
#define A6_VL  59392
#define A6_BYTES 74240

__global__ __launch_bounds__(128, 2) void attn7_kernel(
    const fp16* __restrict__ Qh,
    const fp16* __restrict__ KVh, const fp16* __restrict__ KVl,
    fp16* __restrict__ GF) {
  extern __shared__ __align__(1024) char sm[];
  uint32_t sb = smem_u32(sm);
  int tid = threadIdx.x, lane = tid & 31, warp = tid >> 5;
  int part = blockIdx.x % 7;
  int bh = blockIdx.x / 7;
  int b = bh >> 3, h = bh & 7;
  const fp16* kHh = KVh + ((size_t)b * 2 * DIM + h * 32) * HWP;
  const fp16* kHl = KVl + ((size_t)b * 2 * DIM + h * 32) * HWP;
  const fp16* vHh = kHh + (size_t)DIM * HWP;
  const fp16* vHl = kHl + (size_t)DIM * HWP;
  const float scal = 0.17677669529663687f;  // 32^-0.5

  for (int t = tid; t < 896; t += 128) {
    int d = t & 31, jg = t >> 5;
    int j0 = jg * 8;
    fp16 th[8], tl[8], uh[8], ul[8];
    if (j0 + 8 <= HWP) {
      const char* pkh = (const char*)(kHh + (size_t)d * HWP + j0);
      const char* pkl = (const char*)(kHl + (size_t)d * HWP + j0);
      const char* pvh = (const char*)(vHh + (size_t)d * HWP + j0);
      const char* pvl = (const char*)(vHl + (size_t)d * HWP + j0);
      *(uint2*)th = *(const uint2*)pkh; *(uint2*)(th + 4) = *(const uint2*)(pkh + 8);
      *(uint2*)tl = *(const uint2*)pkl; *(uint2*)(tl + 4) = *(const uint2*)(pkl + 8);
      *(uint2*)uh = *(const uint2*)pvh; *(uint2*)(uh + 4) = *(const uint2*)(pvh + 8);
      *(uint2*)ul = *(const uint2*)pvl; *(uint2*)(ul + 4) = *(const uint2*)(pvl + 8);
    } else {
      fp16 z = __float2half(0.f);
#pragma unroll
      for (int j = 0; j < 8; j++) {
        int g = j0 + j;
        bool v = g < HWP;
        th[j] = v ? kHh[(size_t)d * HWP + g] : z;
        tl[j] = v ? kHl[(size_t)d * HWP + g] : z;
        uh[j] = v ? vHh[(size_t)d * HWP + g] : z;
        ul[j] = v ? vHl[(size_t)d * HWP + g] : z;
      }
    }
#pragma unroll
    for (int j = 0; j < 8; j++) {
      *(fp16*)(sm + A6_KH + ((j0 + j) * 40 + d) * 2) = th[j];
      *(fp16*)(sm + A6_KL + ((j0 + j) * 40 + d) * 2) = tl[j];
    }
    *(uint4*)(sm + A6_VH + (d * 232 + j0) * 2) = *(uint4*)uh;
    *(uint4*)(sm + A6_VL + (d * 232 + j0) * 2) = *(uint4*)ul;
  }

  const fp16* qbh = Qh + ((size_t)b * DIM + h * 32) * HWX;
  fp16* GFb = GF + ((size_t)b * DIM + h * 32) * HWX;
  int mw = warp * 16;

  for (int it = 0; it < 7; it++) {
    int q0 = (part * 7 + it) * 64;
    __syncthreads();
    for (int t = tid; t < 256; t += 128) {
      int d = t & 31, mg = t >> 5;
      uint4 vh = *(const uint4*)(qbh + (size_t)d * HWX + q0 + mg * 8);
      fp16* eh = (fp16*)&vh;
#pragma unroll
      for (int j = 0; j < 8; j++)
        *(fp16*)(sm + A6_AQH + ((mg * 8 + j) * 40 + d) * 2) = eh[j];
    }
    __syncthreads();

    float acc[26][4];
    uint32_t accH[26][2];
#pragma unroll
    for (int nt = 0; nt < 26; nt++) {
#pragma unroll
      for (int c = 0; c < 4; c++) acc[nt][c] = 0.f;
      accH[nt][0] = 0u; accH[nt][1] = 0u;
    }
    int rn = ((lane >> 4) << 3) + (lane & 7);
    uint32_t kb = ((lane >> 3) & 1) * 16;
#pragma unroll
    for (int s = 0; s < 2; s++) {
      uint32_t ah[4];
      uint32_t aoff = ((mw + (lane & 15)) * 40 + s * 16) * 2 + (lane >> 4) * 16;
      ldm4(ah, sb + A6_AQH + aoff);
#pragma unroll
      for (int np = 0; np < 13; np++) {
        uint32_t boff = (uint32_t)(((np * 16 + rn) * 40 + s * 16) * 2) + kb;
        uint32_t bh4[4], bl4[4];
        ldm4(bh4, sb + A6_KH + boff);
        ldm4(bl4, sb + A6_KL + boff);
        mmaF32(acc[2*np],   ah, bh4);
        mmaF16(accH[2*np],  ah, bl4);
        mmaF32(acc[2*np+1], ah, bh4 + 2);
        mmaF16(accH[2*np+1],ah, bl4 + 2);
      }
    }

    float sum1 = 0.f, sum2 = 0.f;
#pragma unroll
    for (int nt = 0; nt < 26; nt++) {
      int jb = nt * 8 + (lane & 3) * 2;
      float e0 = (acc[nt][0] + hlo(accH[nt][0])) * scal;
      float e1 = (acc[nt][1] + hhi(accH[nt][0])) * scal;
      float e2 = (acc[nt][2] + hlo(accH[nt][1])) * scal;
      float e3 = (acc[nt][3] + hhi(accH[nt][1])) * scal;
      e0 = (jb < HWP)     ? __expf(e0) : 0.f;
      e1 = (jb + 1 < HWP) ? __expf(e1) : 0.f;
      e2 = (jb < HWP)     ? __expf(e2) : 0.f;
      e3 = (jb + 1 < HWP) ? __expf(e3) : 0.f;
      acc[nt][0] = e0; acc[nt][1] = e1; acc[nt][2] = e2; acc[nt][3] = e3;
      sum1 += e0 + e1;
      sum2 += e2 + e3;
    }
#pragma unroll
    for (int o = 1; o <= 2; o <<= 1) {
      sum1 += __shfl_xor_sync(0xffffffffu, sum1, o);
      sum2 += __shfl_xor_sync(0xffffffffu, sum2, o);
    }
    float rec1 = 1.f / sum1, rec2 = 1.f / sum2;

    float acc2[4][4];
    uint32_t acc2H[4][2];
#pragma unroll
    for (int nt = 0; nt < 4; nt++) {
#pragma unroll
      for (int c = 0; c < 4; c++) acc2[nt][c] = 0.f;
      acc2H[nt][0] = 0u; acc2H[nt][1] = 0u;
    }
#pragma unroll 1
    for (int k = 0; k < 13; k++) {
      uint32_t ph[4];
      ph[0] = hpack(acc[2*k][0] * rec1,   acc[2*k][1] * rec1);
      ph[1] = hpack(acc[2*k][2] * rec2,   acc[2*k][3] * rec2);
      ph[2] = hpack(acc[2*k+1][0] * rec1, acc[2*k+1][1] * rec1);
      ph[3] = hpack(acc[2*k+1][2] * rec2, acc[2*k+1][3] * rec2);
#pragma unroll
      for (int np = 0; np < 2; np++) {
        uint32_t boff = (uint32_t)(((np * 16 + rn) * 232 + k * 16) * 2) + kb;
        uint32_t vh4[4], vl4[4];
        ldm4(vh4, sb + A6_VH + boff);
        ldm4(vl4, sb + A6_VL + boff);
        mmaF32(acc2[2*np],   ph, vh4);
        mmaF16(acc2H[2*np],  ph, vl4);
        mmaF32(acc2[2*np+1], ph, vh4 + 2);
        mmaF16(acc2H[2*np+1],ph, vl4 + 2);
      }
    }
    __syncthreads();

    float* Ob = (float*)sm;
    {
      int m1 = mw + (lane >> 2), m2 = m1 + 8;
      int cb = (lane & 3) * 2;
#pragma unroll
      for (int nt = 0; nt < 4; nt++) {
        int dcol = nt * 8 + cb;
        Ob[dcol * 68 + m1]       = acc2[nt][0] + hlo(acc2H[nt][0]);
        Ob[(dcol + 1) * 68 + m1] = acc2[nt][1] + hhi(acc2H[nt][0]);
        Ob[dcol * 68 + m2]       = acc2[nt][2] + hlo(acc2H[nt][1]);
        Ob[(dcol + 1) * 68 + m2] = acc2[nt][3] + hhi(acc2H[nt][1]);
      }
    }
    __syncthreads();
    {
      int row = tid >> 2, i0 = (tid & 3) * 16;
#pragma unroll
      for (int c = 0; c < 4; c++) {
        int i = i0 + c * 4;
        float4 v = *(float4*)&Ob[row * 68 + i];
        __half2 p0 = __floats2half2_rn(v.x, v.y);
        __half2 p1 = __floats2half2_rn(v.z, v.w);
        uint2 pk = make_uint2(*(uint32_t*)&p0, *(uint32_t*)&p1);
        *(uint2*)&GFb[(size_t)row * HWX + q0 + i] = pk;
      }
    }
  }
}

extern "C" void kernel_launch(void* const* d_in, const int* in_sizes, int n_in,
                              void* d_out, int out_size) {
  const float* x     = (const float*)d_in[0];
  const float* q_w   = (const float*)d_in[1];
  const float* q_b   = (const float*)d_in[2];
  const float* kv_w  = (const float*)d_in[3];
  const float* kv_b  = (const float*)d_in[4];
  const float* p0_w  = (const float*)d_in[5];
  const float* p0_b  = (const float*)d_in[6];
  const float* bn0_g = (const float*)d_in[7];
  const float* bn0_b = (const float*)d_in[8];
  const float* bn0_m = (const float*)d_in[9];
  const float* bn0_v = (const float*)d_in[10];
  const float* pl0_w = (const float*)d_in[11];
  const float* pl0_b = (const float*)d_in[12];
  const float* p1_w  = (const float*)d_in[13];
  const float* p1_b  = (const float*)d_in[14];
  const float* bn1_g = (const float*)d_in[15];
  const float* bn1_b = (const float*)d_in[16];
  const float* bn1_m = (const float*)d_in[17];
  const float* bn1_v = (const float*)d_in[18];
  const float* loc_w = (const float*)d_in[19];
  const float* loc_b = (const float*)d_in[20];
  const float* mix_w = (const float*)d_in[21];
  const float* mix_b = (const float*)d_in[22];
  float* out = (float*)d_out;

  fp16 *xh, *qh, *mh, *gf16, *p0h, *pm16, *pfh, *kvh, *kvl, *wh, *wl;
  cudaGetSymbolAddress((void**)&xh, g_xh);
  cudaGetSymbolAddress((void**)&qh, g_qh);
  cudaGetSymbolAddress((void**)&mh, g_mh);
  cudaGetSymbolAddress((void**)&gf16, g_gf16);
  cudaGetSymbolAddress((void**)&p0h, g_p0h);
  cudaGetSymbolAddress((void**)&pm16, g_pm16);
  cudaGetSymbolAddress((void**)&pfh, g_pfh);
  cudaGetSymbolAddress((void**)&kvh, g_kvh); cudaGetSymbolAddress((void**)&kvl, g_kvl);
  cudaGetSymbolAddress((void**)&wh, g_wh);   cudaGetSymbolAddress((void**)&wl, g_wl);

  cudaFuncSetAttribute(conv1x1_hf_kernel, cudaFuncAttributeMaxDynamicSharedMemorySize, CV_SMEM);
  cudaFuncSetAttribute(attn7_kernel, cudaFuncAttributeMaxDynamicSharedMemorySize, A6_BYTES);

  // 0. pre-split: all weights in one launch; x hi
  cvt_h_kernel<<<(NX/4 + 255)/256, 256>>>(x, xh, NX/4);
  cvt_w_kernel<<<(NW/4 + 255)/256, 256>>>(q_w, pl0_w, kv_w, mix_w, wh, wl);

  // 1. q_local -> fp16 hi (attention Q + gate input)
  conv1x1_hf_kernel<<<dim3((HWX + 127)/128, DIM/128, BATCH), 256, CV_SMEM>>>(
      wh + WOFF_Q, wl + WOFF_Q, xh, q_b, (float*)nullptr, qh, (fp16*)nullptr, DIM, DIM, HWX);
  // 2. p0 = BN0(dw5x5_s2(x)) -> fp16 (smem-tiled)
  dw1_tiled_kernel<<<BATCH*DIM, 256>>>(x, p0_w, p0_b, bn0_g, bn0_b, bn0_m, bn0_v, p0h);
  // 3. pmid = conv1x1(p0) -> fp16
  conv1x1_hf_kernel<<<dim3((HW1 + 127)/128, DIM/128, BATCH), 256, CV_SMEM>>>(
      wh + WOFF_PL, wl + WOFF_PL, p0h, pl0_b, (float*)nullptr, pm16, (fp16*)nullptr, DIM, DIM, HW1);
  // 4. pfin = BN1(dw5x5_s2(pmid)) -> fp16 (smem-tiled)
  dw2_tiled_kernel<<<BATCH*DIM, 256>>>(pm16, p1_w, p1_b, bn1_g, bn1_b, bn1_m, bn1_v, pfh);
  // 5. kv = conv1x1(pfin) -> fp16 hi/lo
  conv1x1_hf_kernel<<<dim3((HWP + 127)/128, (2*DIM)/128, BATCH), 256, CV_SMEM>>>(
      wh + WOFF_KV, wl + WOFF_KV, pfh, kv_b, (float*)nullptr, kvh, kvl, 2*DIM, DIM, HWP);
  // 6. attention -> gf16
  attn7_kernel<<<BATCH*HEADS*7, 128, A6_BYTES>>>(qh, kvh, kvl, gf16);
  // 7. local mixer + gating (smem-tiled) -> mh
  gate_tiled_kernel<<<BATCH*DIM, 256>>>(qh, loc_w, loc_b, gf16, mh);
  // 8. out = conv1x1(mixbuf) -> f32
  conv1x1_hf_kernel<<<dim3((HWX + 127)/128, DIM/128, BATCH), 256, CV_SMEM>>>(
      wh + WOFF_MIX, wl + WOFF_MIX, mh, mix_b, out, (fp16*)nullptr, (fp16*)nullptr, DIM, DIM, HWX);
}

// round 14
// speedup vs baseline: 1.4313x; 1.4313x over previous
#include <cuda_runtime.h>
#include <cuda_fp16.h>
#include <cstdint>

#define BATCH 16
#define DIM 256
#define HH 56
#define WW 56
#define HWX (HH*WW)          // 3136
#define HEADS 8
#define DH 32
#define HP1 28
#define HW1 (HP1*HP1)        // 784
#define HP2 14
#define HWP (HP2*HP2)        // 196
#define BN_EPS 1e-5f

#define SW128(x) ((x) ^ (((x) >> 3) & 0x70))

typedef __half fp16;

__device__ __forceinline__ uint32_t smem_u32(const void* p) {
  uint32_t a;
  asm("{ .reg .u64 t; cvta.to.shared.u64 t, %1; cvt.u32.u64 %0, t; }" : "=r"(a) : "l"(p));
  return a;
}
__device__ __forceinline__ void ldm4(uint32_t a[4], uint32_t addr) {
  asm volatile("ldmatrix.sync.aligned.m8n8.x4.shared.b16 {%0,%1,%2,%3}, [%4];"
               : "=r"(a[0]), "=r"(a[1]), "=r"(a[2]), "=r"(a[3]) : "r"(addr));
}
__device__ __forceinline__ void ldm4t(uint32_t a[4], uint32_t addr) {
  asm volatile("ldmatrix.sync.aligned.m8n8.x4.trans.shared.b16 {%0,%1,%2,%3}, [%4];"
               : "=r"(a[0]), "=r"(a[1]), "=r"(a[2]), "=r"(a[3]) : "r"(addr));
}
__device__ __forceinline__ void mmaF32(float d[4], const uint32_t a[4], const uint32_t b[2]) {
  asm volatile("mma.sync.aligned.m16n8k16.row.col.f32.f16.f16.f32 "
               "{%0,%1,%2,%3}, {%4,%5,%6,%7}, {%8,%9}, {%0,%1,%2,%3};"
               : "+f"(d[0]), "+f"(d[1]), "+f"(d[2]), "+f"(d[3])
               : "r"(a[0]), "r"(a[1]), "r"(a[2]), "r"(a[3]), "r"(b[0]), "r"(b[1]));
}
__device__ __forceinline__ void mmaF16(uint32_t d[2], const uint32_t a[4], const uint32_t b[2]) {
  asm volatile("mma.sync.aligned.m16n8k16.row.col.f16.f16.f16.f16 "
               "{%0,%1}, {%2,%3,%4,%5}, {%6,%7}, {%0,%1};"
               : "+r"(d[0]), "+r"(d[1])
               : "r"(a[0]), "r"(a[1]), "r"(a[2]), "r"(a[3]), "r"(b[0]), "r"(b[1]));
}
__device__ __forceinline__ uint32_t hpack(float a, float b) {
  __half2 t = __floats2half2_rn(a, b);
  return *(uint32_t*)&t;
}
__device__ __forceinline__ float hlo(uint32_t v) { return __half2float(((__half2*)&v)->x); }
__device__ __forceinline__ float hhi(uint32_t v) { return __half2float(((__half2*)&v)->y); }

// ---------------- scratch (device globals; no allocations allowed) ----------------
#define NX (BATCH*DIM*HWX)
#define NP0 (BATCH*DIM*HW1)
#define NPF (BATCH*DIM*HWP)
#define NKV (BATCH*2*DIM*HWP)
#define WOFF_Q 0
#define WOFF_PL 65536
#define WOFF_KV 131072
#define WOFF_MIX 262144
#define NW 327680
__device__ fp16 g_xh[NX];
__device__ fp16 g_qh[NX];
__device__ fp16 g_mh[NX];
__device__ fp16 g_gf16[NX];
__device__ fp16 g_p0h[NP0];
__device__ fp16 g_pm16[NP0];
__device__ fp16 g_pfh[NPF];
__device__ fp16 g_kvh[NKV], g_kvl[NKV];
__device__ fp16 g_wh[NW],  g_wl[NW];

// ---------------- x -> fp16 hi ----------------
__global__ __launch_bounds__(256) void cvt_h_kernel(
    const float* __restrict__ s, fp16* __restrict__ h, int n4) {
  int i = blockIdx.x * 256 + threadIdx.x;
  if (i >= n4) return;
  float4 v = ((const float4*)s)[i];
  ((__half2*)h)[2*i]   = __floats2half2_rn(v.x, v.y);
  ((__half2*)h)[2*i+1] = __floats2half2_rn(v.z, v.w);
}
// ---------------- fused weight hi/lo split ----------------
__global__ __launch_bounds__(256) void cvt_w_kernel(
    const float* __restrict__ qw, const float* __restrict__ plw,
    const float* __restrict__ kvw, const float* __restrict__ mxw,
    fp16* __restrict__ h, fp16* __restrict__ l) {
  int i = blockIdx.x * 256 + threadIdx.x;
  if (i >= NW / 4) return;
  const float* src;
  int li;
  if (i < 16384)      { src = qw;  li = i; }
  else if (i < 32768) { src = plw; li = i - 16384; }
  else if (i < 65536) { src = kvw; li = i - 32768; }
  else                { src = mxw; li = i - 65536; }
  float4 v = ((const float4*)src)[li];
  __half2 h0 = __floats2half2_rn(v.x, v.y);
  __half2 h1 = __floats2half2_rn(v.z, v.w);
  __half2 l0 = __floats2half2_rn(v.x - __half2float(h0.x), v.y - __half2float(h0.y));
  __half2 l1 = __floats2half2_rn(v.z - __half2float(h1.x), v.w - __half2float(h1.y));
  ((__half2*)h)[2*i] = h0; ((__half2*)h)[2*i+1] = h1;
  ((__half2*)l)[2*i] = l0; ((__half2*)l)[2*i+1] = l1;
}

// ---------------- 1x1 conv: 2-pass split-fp16 HMMA, x4-trans B loads ----------------
#define CV_SMEM 49152

__global__ __launch_bounds__(256) void conv1x1_hf_kernel(
    const fp16* __restrict__ Ah, const fp16* __restrict__ Al,
    const fp16* __restrict__ Bh,
    const float* __restrict__ bias, float* __restrict__ Yf,
    fp16* __restrict__ Yh, fp16* __restrict__ Yl,
    int CO, int CI, int HW) {
  extern __shared__ __align__(1024) char smem[];
  char* sAh = smem;         char* sAl = smem + 16384;
  char* sBh = smem + 32768;
  uint32_t aAh = smem_u32(sAh), aAl = smem_u32(sAl);
  uint32_t aBh = smem_u32(sBh);
  int tid = threadIdx.x, lane = tid & 31, wid = tid >> 5;
  int m0 = blockIdx.y * 128, n0 = blockIdx.x * 128;
  const fp16* Bhb = Bh + (size_t)blockIdx.z * CI * HW;
  int mw = (wid & 3) * 32, nw = (wid >> 2) * 64;

  float acc[2][8][4];
  uint32_t accH[2][8][2];
#pragma unroll
  for (int i = 0; i < 2; i++)
#pragma unroll
    for (int j = 0; j < 8; j++) {
#pragma unroll
      for (int c = 0; c < 4; c++) acc[i][j][c] = 0.f;
      accH[i][j][0] = 0u; accH[i][j][1] = 0u;
    }

  for (int k0 = 0; k0 < CI; k0 += 64) {
#pragma unroll
    for (int i = 0; i < 4; i++) {
      int t = tid + i * 256;
      int m = t >> 3, kg = t & 7;
      size_t src = (size_t)(m0 + m) * CI + k0 + kg * 8;
      uint32_t dst = SW128(m * 128 + kg * 16);
      *(uint4*)(sAh + dst) = *(const uint4*)(Ah + src);
      *(uint4*)(sAl + dst) = *(const uint4*)(Al + src);
    }
#pragma unroll
    for (int i = 0; i < 4; i++) {
      int t = tid + i * 256;
      int k = t & 63, c = t >> 6;
      int gn = n0 + c * 8;
      uint4 vh;
      if (gn + 8 <= HW) {
        const char* ph = (const char*)(Bhb + (size_t)(k0 + k) * HW + gn);
        uint2 h0 = *(const uint2*)ph, h1 = *(const uint2*)(ph + 8);
        vh = make_uint4(h0.x, h0.y, h1.x, h1.y);
      } else {
        fp16 th[8];
#pragma unroll
        for (int j = 0; j < 8; j++) {
          int g = gn + j;
          th[j] = (g < HW) ? Bhb[(size_t)(k0 + k) * HW + g] : __float2half(0.f);
        }
        vh = *(uint4*)th;
      }
      *(uint4*)(sBh + (k * 256 + ((c ^ (k & 15)) << 4))) = vh;
    }
    __syncthreads();
#pragma unroll
    for (int s = 0; s < 4; s++) {
      uint32_t ah[2][4], al[2][4];
#pragma unroll
      for (int tm = 0; tm < 2; tm++) {
        uint32_t off = SW128((mw + tm * 16 + (lane & 15)) * 128 + s * 32 + (lane >> 4) * 16);
        ldm4(ah[tm], aAh + off);
        ldm4(al[tm], aAl + off);
      }
      int kk = s * 16 + (lane & 15);
#pragma unroll
      for (int ntp = 0; ntp < 4; ntp++) {
        int nt_eff = 2 * ntp + (lane >> 4);
        uint32_t cIdx = (uint32_t)(((nw >> 3) + nt_eff) ^ (kk & 15));
        uint32_t bq[4];
        ldm4t(bq, aBh + kk * 256 + (cIdx << 4));
#pragma unroll
        for (int tm = 0; tm < 2; tm++) {
          mmaF32(acc[tm][2*ntp],   ah[tm], bq);
          mmaF16(accH[tm][2*ntp],  al[tm], bq);
          mmaF32(acc[tm][2*ntp+1], ah[tm], bq + 2);
          mmaF16(accH[tm][2*ntp+1],al[tm], bq + 2);
        }
      }
    }
    __syncthreads();
  }
#pragma unroll
  for (int tm = 0; tm < 2; tm++) {
    int r0 = m0 + mw + tm * 16 + (lane >> 2);
    float b0 = bias[r0], b1 = bias[r0 + 8];
#pragma unroll
    for (int tn = 0; tn < 8; tn++) {
      int col = n0 + nw + tn * 8 + (lane & 3) * 2;
      if (col < HW) {
        float o0 = acc[tm][tn][0] + hlo(accH[tm][tn][0]) + b0;
        float o1 = acc[tm][tn][1] + hhi(accH[tm][tn][0]) + b0;
        float o2 = acc[tm][tn][2] + hlo(accH[tm][tn][1]) + b1;
        float o3 = acc[tm][tn][3] + hhi(accH[tm][tn][1]) + b1;
        size_t i0 = (size_t)blockIdx.z * CO * HW + (size_t)r0 * HW + col;
        size_t i1 = i0 + (size_t)8 * HW;
        if (Yf) {
          *(float2*)&Yf[i0] = make_float2(o0, o1);
          *(float2*)&Yf[i1] = make_float2(o2, o3);
        }
        if (Yh) {
          __half2 h0 = __floats2half2_rn(o0, o1);
          __half2 h1 = __floats2half2_rn(o2, o3);
          *(__half2*)&Yh[i0] = h0; *(__half2*)&Yh[i1] = h1;
          if (Yl) {
            __half2 l0 = __floats2half2_rn(o0 - __half2float(h0.x), o1 - __half2float(h0.y));
            __half2 l1 = __floats2half2_rn(o2 - __half2float(h1.x), o3 - __half2float(h1.y));
            *(__half2*)&Yl[i0] = l0; *(__half2*)&Yl[i1] = l1;
          }
        }
      }
    }
  }
}

// ---------------- depthwise 5x5 stride2 + BN, fp32 in -> fp16 (1-wide, coalesced) -----
__global__ __launch_bounds__(256) void dw_s2_bn_f1_kernel(
    const float* __restrict__ X, const float* __restrict__ Wd,
    const float* __restrict__ bias, const float* __restrict__ gam,
    const float* __restrict__ bet, const float* __restrict__ mu,
    const float* __restrict__ var, fp16* __restrict__ Yh,
    int Hin, int Win, int Hout, int Wout) {
  int idx = blockIdx.x * 256 + threadIdx.x;
  int total = BATCH * DIM * Hout * Wout;
  if (idx >= total) return;
  int ox = idx % Wout; int t = idx / Wout;
  int oy = t % Hout; t /= Hout;
  int c = t % DIM; int b = t / DIM;
  const float* xp = X + (size_t)(b * DIM + c) * Hin * Win;
  const float* wp = Wd + c * 25;
  float s = 0.f;
#pragma unroll
  for (int ky = 0; ky < 5; ky++) {
    int iy = oy * 2 - 2 + ky;
    if (iy < 0 || iy >= Hin) continue;
#pragma unroll
    for (int kx = 0; kx < 5; kx++) {
      int ix = ox * 2 - 2 + kx;
      if (ix < 0 || ix >= Win) continue;
      s += xp[iy * Win + ix] * wp[ky * 5 + kx];
    }
  }
  s += bias[c];
  float sc = gam[c] * rsqrtf(var[c] + BN_EPS);
  Yh[idx] = __float2half_rn((s - mu[c]) * sc + bet[c]);
}

// ---------------- depthwise 5x5 stride2 + BN, fp16 in -> fp16 (1-wide) ----------------
__global__ __launch_bounds__(256) void dw_s2_bn_h1_kernel(
    const fp16* __restrict__ X, const float* __restrict__ Wd,
    const float* __restrict__ bias, const float* __restrict__ gam,
    const float* __restrict__ bet, const float* __restrict__ mu,
    const float* __restrict__ var, fp16* __restrict__ Yh,
    int Hin, int Win, int Hout, int Wout) {
  int idx = blockIdx.x * 256 + threadIdx.x;
  int total = BATCH * DIM * Hout * Wout;
  if (idx >= total) return;
  int ox = idx % Wout; int t = idx / Wout;
  int oy = t % Hout; t /= Hout;
  int c = t % DIM; int b = t / DIM;
  const fp16* xp = X + (size_t)(b * DIM + c) * Hin * Win;
  const float* wp = Wd + c * 25;
  float s = 0.f;
#pragma unroll
  for (int ky = 0; ky < 5; ky++) {
    int iy = oy * 2 - 2 + ky;
    if (iy < 0 || iy >= Hin) continue;
#pragma unroll
    for (int kx = 0; kx < 5; kx++) {
      int ix = ox * 2 - 2 + kx;
      if (ix < 0 || ix >= Win) continue;
      s += __half2float(xp[iy * Win + ix]) * wp[ky * 5 + kx];
    }
  }
  s += bias[c];
  float sc = gam[c] * rsqrtf(var[c] + BN_EPS);
  Yh[idx] = __float2half_rn((s - mu[c]) * sc + bet[c]);
}

// ---------------- local mixer, fp16 in/out (1-wide, coalesced) ----------------
__global__ __launch_bounds__(256) void local_gate_h1_kernel(
    const fp16* __restrict__ Q, const float* __restrict__ Wd,
    const float* __restrict__ bias, const fp16* __restrict__ G,
    fp16* __restrict__ Oh) {
  int idx = blockIdx.x * 256 + threadIdx.x;
  int total = BATCH * DIM * HWX;
  if (idx >= total) return;
  int ox = idx % WW; int t = idx / WW;
  int oy = t % HH; t /= HH;
  int c = t % DIM; int b = t / DIM;
  const fp16* xp = Q + (size_t)(b * DIM + c) * HWX;
  const float* wp = Wd + c * 25;
  float s = 0.f;
#pragma unroll
  for (int ky = 0; ky < 5; ky++) {
    int iy = oy + ky - 2;
    if (iy < 0 || iy >= HH) continue;
#pragma unroll
    for (int kx = 0; kx < 5; kx++) {
      int ix = ox + kx - 2;
      if (ix < 0 || ix >= WW) continue;
      s += __half2float(xp[iy * WW + ix]) * wp[ky * 5 + kx];
    }
  }
  s += bias[c];
  float lf = s / (1.f + __expf(-s));
  float gv = __half2float(G[idx]);
  float sg = 1.f / (1.f + __expf(-gv));
  Oh[idx] = __float2half_rn(lf * sg * gv);
}

// ---------------- attention v7: x4 B-loads, no max-pass, fp16 output ----------------
#define A6_AQH 0
#define A6_KH  8704
#define A6_KL  26624
#define A6_VH  44544
#define A6_VL  59392
#define A6_BYTES 74240

__global__ __launch_bounds__(128, 2) void attn7_kernel(
    const fp16* __restrict__ Qh,
    const fp16* __restrict__ KVh, const fp16* __restrict__ KVl,
    fp16* __restrict__ GF) {
  extern __shared__ __align__(1024) char sm[];
  uint32_t sb = smem_u32(sm);
  int tid = threadIdx.x, lane = tid & 31, warp = tid >> 5;
  int part = blockIdx.x % 7;
  int bh = blockIdx.x / 7;
  int b = bh >> 3, h = bh & 7;
  const fp16* kHh = KVh + ((size_t)b * 2 * DIM + h * 32) * HWP;
  const fp16* kHl = KVl + ((size_t)b * 2 * DIM + h * 32) * HWP;
  const fp16* vHh = kHh + (size_t)DIM * HWP;
  const fp16* vHl = kHl + (size_t)DIM * HWP;
  const float scal = 0.17677669529663687f;  // 32^-0.5

  for (int t = tid; t < 896; t += 128) {
    int d = t & 31, jg = t >> 5;
    int j0 = jg * 8;
    fp16 th[8], tl[8], uh[8], ul[8];
    if (j0 + 8 <= HWP) {
      const char* pkh = (const char*)(kHh + (size_t)d * HWP + j0);
      const char* pkl = (const char*)(kHl + (size_t)d * HWP + j0);
      const char* pvh = (const char*)(vHh + (size_t)d * HWP + j0);
      const char* pvl = (const char*)(vHl + (size_t)d * HWP + j0);
      *(uint2*)th = *(const uint2*)pkh; *(uint2*)(th + 4) = *(const uint2*)(pkh + 8);
      *(uint2*)tl = *(const uint2*)pkl; *(uint2*)(tl + 4) = *(const uint2*)(pkl + 8);
      *(uint2*)uh = *(const uint2*)pvh; *(uint2*)(uh + 4) = *(const uint2*)(pvh + 8);
      *(uint2*)ul = *(const uint2*)pvl; *(uint2*)(ul + 4) = *(const uint2*)(pvl + 8);
    } else {
      fp16 z = __float2half(0.f);
#pragma unroll
      for (int j = 0; j < 8; j++) {
        int g = j0 + j;
        bool v = g < HWP;
        th[j] = v ? kHh[(size_t)d * HWP + g] : z;
        tl[j] = v ? kHl[(size_t)d * HWP + g] : z;
        uh[j] = v ? vHh[(size_t)d * HWP + g] : z;
        ul[j] = v ? vHl[(size_t)d * HWP + g] : z;
      }
    }
#pragma unroll
    for (int j = 0; j < 8; j++) {
      *(fp16*)(sm + A6_KH + ((j0 + j) * 40 + d) * 2) = th[j];
      *(fp16*)(sm + A6_KL + ((j0 + j) * 40 + d) * 2) = tl[j];
    }
    *(uint4*)(sm + A6_VH + (d * 232 + j0) * 2) = *(uint4*)uh;
    *(uint4*)(sm + A6_VL + (d * 232 + j0) * 2) = *(uint4*)ul;
  }

  const fp16* qbh = Qh + ((size_t)b * DIM + h * 32) * HWX;
  fp16* GFb = GF + ((size_t)b * DIM + h * 32) * HWX;
  int mw = warp * 16;

  for (int it = 0; it < 7; it++) {
    int q0 = (part * 7 + it) * 64;
    __syncthreads();
    for (int t = tid; t < 256; t += 128) {
      int d = t & 31, mg = t >> 5;
      uint4 vh = *(const uint4*)(qbh + (size_t)d * HWX + q0 + mg * 8);
      fp16* eh = (fp16*)&vh;
#pragma unroll
      for (int j = 0; j < 8; j++)
        *(fp16*)(sm + A6_AQH + ((mg * 8 + j) * 40 + d) * 2) = eh[j];
    }
    __syncthreads();

    float acc[26][4];
    uint32_t accH[26][2];
#pragma unroll
    for (int nt = 0; nt < 26; nt++) {
#pragma unroll
      for (int c = 0; c < 4; c++) acc[nt][c] = 0.f;
      accH[nt][0] = 0u; accH[nt][1] = 0u;
    }
    int rn = ((lane >> 4) << 3) + (lane & 7);
    uint32_t kb = ((lane >> 3) & 1) * 16;
#pragma unroll
    for (int s = 0; s < 2; s++) {
      uint32_t ah[4];
      uint32_t aoff = ((mw + (lane & 15)) * 40 + s * 16) * 2 + (lane >> 4) * 16;
      ldm4(ah, sb + A6_AQH + aoff);
#pragma unroll
      for (int np = 0; np < 13; np++) {
        uint32_t boff = (uint32_t)(((np * 16 + rn) * 40 + s * 16) * 2) + kb;
        uint32_t bh4[4], bl4[4];
        ldm4(bh4, sb + A6_KH + boff);
        ldm4(bl4, sb + A6_KL + boff);
        mmaF32(acc[2*np],   ah, bh4);
        mmaF16(accH[2*np],  ah, bl4);
        mmaF32(acc[2*np+1], ah, bh4 + 2);
        mmaF16(accH[2*np+1],ah, bl4 + 2);
      }
    }

    float sum1 = 0.f, sum2 = 0.f;
#pragma unroll
    for (int nt = 0; nt < 26; nt++) {
      int jb = nt * 8 + (lane & 3) * 2;
      float e0 = (acc[nt][0] + hlo(accH[nt][0])) * scal;
      float e1 = (acc[nt][1] + hhi(accH[nt][0])) * scal;
      float e2 = (acc[nt][2] + hlo(accH[nt][1])) * scal;
      float e3 = (acc[nt][3] + hhi(accH[nt][1])) * scal;
      e0 = (jb < HWP)     ? __expf(e0) : 0.f;
      e1 = (jb + 1 < HWP) ? __expf(e1) : 0.f;
      e2 = (jb < HWP)     ? __expf(e2) : 0.f;
      e3 = (jb + 1 < HWP) ? __expf(e3) : 0.f;
      acc[nt][0] = e0; acc[nt][1] = e1; acc[nt][2] = e2; acc[nt][3] = e3;
      sum1 += e0 + e1;
      sum2 += e2 + e3;
    }
#pragma unroll
    for (int o = 1; o <= 2; o <<= 1) {
      sum1 += __shfl_xor_sync(0xffffffffu, sum1, o);
      sum2 += __shfl_xor_sync(0xffffffffu, sum2, o);
    }
    float rec1 = 1.f / sum1, rec2 = 1.f / sum2;

    float acc2[4][4];
    uint32_t acc2H[4][2];
#pragma unroll
    for (int nt = 0; nt < 4; nt++) {
#pragma unroll
      for (int c = 0; c < 4; c++) acc2[nt][c] = 0.f;
      acc2H[nt][0] = 0u; acc2H[nt][1] = 0u;
    }
#pragma unroll 1
    for (int k = 0; k < 13; k++) {
      uint32_t ph[4];
      ph[0] = hpack(acc[2*k][0] * rec1,   acc[2*k][1] * rec1);
      ph[1] = hpack(acc[2*k][2] * rec2,   acc[2*k][3] * rec2);
      ph[2] = hpack(acc[2*k+1][0] * rec1, acc[2*k+1][1] * rec1);
      ph[3] = hpack(acc[2*k+1][2] * rec2, acc[2*k+1][3] * rec2);
#pragma unroll
      for (int np = 0; np < 2; np++) {
        uint32_t boff = (uint32_t)(((np * 16 + rn) * 232 + k * 16) * 2) + kb;
        uint32_t vh4[4], vl4[4];
        ldm4(vh4, sb + A6_VH + boff);
        ldm4(vl4, sb + A6_VL + boff);
        mmaF32(acc2[2*np],   ph, vh4);
        mmaF16(acc2H[2*np],  ph, vl4);
        mmaF32(acc2[2*np+1], ph, vh4 + 2);
        mmaF16(acc2H[2*np+1],ph, vl4 + 2);
      }
    }
    __syncthreads();

    float* Ob = (float*)sm;
    {
      int m1 = mw + (lane >> 2), m2 = m1 + 8;
      int cb = (lane & 3) * 2;
#pragma unroll
      for (int nt = 0; nt < 4; nt++) {
        int dcol = nt * 8 + cb;
        Ob[dcol * 68 + m1]       = acc2[nt][0] + hlo(acc2H[nt][0]);
        Ob[(dcol + 1) * 68 + m1] = acc2[nt][1] + hhi(acc2H[nt][0]);
        Ob[dcol * 68 + m2]       = acc2[nt][2] + hlo(acc2H[nt][1]);
        Ob[(dcol + 1) * 68 + m2] = acc2[nt][3] + hhi(acc2H[nt][1]);
      }
    }
    __syncthreads();
    {
      int row = tid >> 2, i0 = (tid & 3) * 16;
#pragma unroll
      for (int c = 0; c < 4; c++) {
        int i = i0 + c * 4;
        float4 v = *(float4*)&Ob[row * 68 + i];
        __half2 p0 = __floats2half2_rn(v.x, v.y);
        __half2 p1 = __floats2half2_rn(v.z, v.w);
        uint2 pk = make_uint2(*(uint32_t*)&p0, *(uint32_t*)&p1);
        *(uint2*)&GFb[(size_t)row * HWX + q0 + i] = pk;
      }
    }
  }
}

extern "C" void kernel_launch(void* const* d_in, const int* in_sizes, int n_in,
                              void* d_out, int out_size) {
  const float* x     = (const float*)d_in[0];
  const float* q_w   = (const float*)d_in[1];
  const float* q_b   = (const float*)d_in[2];
  const float* kv_w  = (const float*)d_in[3];
  const float* kv_b  = (const float*)d_in[4];
  const float* p0_w  = (const float*)d_in[5];
  const float* p0_b  = (const float*)d_in[6];
  const float* bn0_g = (const float*)d_in[7];
  const float* bn0_b = (const float*)d_in[8];
  const float* bn0_m = (const float*)d_in[9];
  const float* bn0_v = (const float*)d_in[10];
  const float* pl0_w = (const float*)d_in[11];
  const float* pl0_b = (const float*)d_in[12];
  const float* p1_w  = (const float*)d_in[13];
  const float* p1_b  = (const float*)d_in[14];
  const float* bn1_g = (const float*)d_in[15];
  const float* bn1_b = (const float*)d_in[16];
  const float* bn1_m = (const float*)d_in[17];
  const float* bn1_v = (const float*)d_in[18];
  const float* loc_w = (const float*)d_in[19];
  const float* loc_b = (const float*)d_in[20];
  const float* mix_w = (const float*)d_in[21];
  const float* mix_b = (const float*)d_in[22];
  float* out = (float*)d_out;

  fp16 *xh, *qh, *mh, *gf16, *p0h, *pm16, *pfh, *kvh, *kvl, *wh, *wl;
  cudaGetSymbolAddress((void**)&xh, g_xh);
  cudaGetSymbolAddress((void**)&qh, g_qh);
  cudaGetSymbolAddress((void**)&mh, g_mh);
  cudaGetSymbolAddress((void**)&gf16, g_gf16);
  cudaGetSymbolAddress((void**)&p0h, g_p0h);
  cudaGetSymbolAddress((void**)&pm16, g_pm16);
  cudaGetSymbolAddress((void**)&pfh, g_pfh);
  cudaGetSymbolAddress((void**)&kvh, g_kvh); cudaGetSymbolAddress((void**)&kvl, g_kvl);
  cudaGetSymbolAddress((void**)&wh, g_wh);   cudaGetSymbolAddress((void**)&wl, g_wl);

  cudaFuncSetAttribute(conv1x1_hf_kernel, cudaFuncAttributeMaxDynamicSharedMemorySize, CV_SMEM);
  cudaFuncSetAttribute(attn7_kernel, cudaFuncAttributeMaxDynamicSharedMemorySize, A6_BYTES);

  // 0. pre-split: all weights in one launch; x hi
  cvt_h_kernel<<<(NX/4 + 255)/256, 256>>>(x, xh, NX/4);
  cvt_w_kernel<<<(NW/4 + 255)/256, 256>>>(q_w, pl0_w, kv_w, mix_w, wh, wl);

  // 1. q_local -> fp16 hi (attention Q + gate input)
  conv1x1_hf_kernel<<<dim3((HWX + 127)/128, DIM/128, BATCH), 256, CV_SMEM>>>(
      wh + WOFF_Q, wl + WOFF_Q, xh, q_b, (float*)nullptr, qh, (fp16*)nullptr, DIM, DIM, HWX);
  // 2. p0 = BN0(dw5x5_s2(x)) -> fp16 (1-wide, coalesced)
  dw_s2_bn_f1_kernel<<<(BATCH*DIM*HW1 + 255)/256, 256>>>(
      x, p0_w, p0_b, bn0_g, bn0_b, bn0_m, bn0_v, p0h, HH, WW, HP1, HP1);
  // 3. pmid = conv1x1(p0) -> fp16
  conv1x1_hf_kernel<<<dim3((HW1 + 127)/128, DIM/128, BATCH), 256, CV_SMEM>>>(
      wh + WOFF_PL, wl + WOFF_PL, p0h, pl0_b, (float*)nullptr, pm16, (fp16*)nullptr, DIM, DIM, HW1);
  // 4. pfin = BN1(dw5x5_s2(pmid)) -> fp16 (1-wide)
  dw_s2_bn_h1_kernel<<<(BATCH*DIM*HWP + 255)/256, 256>>>(
      pm16, p1_w, p1_b, bn1_g, bn1_b, bn1_m, bn1_v, pfh, HP1, HP1, HP2, HP2);
  // 5. kv = conv1x1(pfin) -> fp16 hi/lo
  conv1x1_hf_kernel<<<dim3((HWP + 127)/128, (2*DIM)/128, BATCH), 256, CV_SMEM>>>(
      wh + WOFF_KV, wl + WOFF_KV, pfh, kv_b, (float*)nullptr, kvh, kvl, 2*DIM, DIM, HWP);
  // 6. attention -> gf16
  attn7_kernel<<<BATCH*HEADS*7, 128, A6_BYTES>>>(qh, kvh, kvl, gf16);
  // 7. local mixer + gating (1-wide, coalesced) -> mh
  local_gate_h1_kernel<<<(BATCH*DIM*HWX + 255)/256, 256>>>(qh, loc_w, loc_b, gf16, mh);
  // 8. out = conv1x1(mixbuf) -> f32
  conv1x1_hf_kernel<<<dim3((HWX + 127)/128, DIM/128, BATCH), 256, CV_SMEM>>>(
      wh + WOFF_MIX, wl + WOFF_MIX, mh, mix_b, out, (fp16*)nullptr, (fp16*)nullptr, DIM, DIM, HWX);
}

// round 15
// speedup vs baseline: 1.6792x; 1.1733x over previous
#include <cuda_runtime.h>
#include <cuda_fp16.h>
#include <cstdint>

#define BATCH 16
#define DIM 256
#define HH 56
#define WW 56
#define HWX (HH*WW)          // 3136
#define HEADS 8
#define DH 32
#define HP1 28
#define HW1 (HP1*HP1)        // 784
#define HP2 14
#define HWP (HP2*HP2)        // 196
#define BN_EPS 1e-5f

#define SW128(x) ((x) ^ (((x) >> 3) & 0x70))

typedef __half fp16;

__device__ __forceinline__ uint32_t smem_u32(const void* p) {
  uint32_t a;
  asm("{ .reg .u64 t; cvta.to.shared.u64 t, %1; cvt.u32.u64 %0, t; }" : "=r"(a) : "l"(p));
  return a;
}
__device__ __forceinline__ void ldm4(uint32_t a[4], uint32_t addr) {
  asm volatile("ldmatrix.sync.aligned.m8n8.x4.shared.b16 {%0,%1,%2,%3}, [%4];"
               : "=r"(a[0]), "=r"(a[1]), "=r"(a[2]), "=r"(a[3]) : "r"(addr));
}
__device__ __forceinline__ void ldm4t(uint32_t a[4], uint32_t addr) {
  asm volatile("ldmatrix.sync.aligned.m8n8.x4.trans.shared.b16 {%0,%1,%2,%3}, [%4];"
               : "=r"(a[0]), "=r"(a[1]), "=r"(a[2]), "=r"(a[3]) : "r"(addr));
}
__device__ __forceinline__ void mmaF32(float d[4], const uint32_t a[4], const uint32_t b[2]) {
  asm volatile("mma.sync.aligned.m16n8k16.row.col.f32.f16.f16.f32 "
               "{%0,%1,%2,%3}, {%4,%5,%6,%7}, {%8,%9}, {%0,%1,%2,%3};"
               : "+f"(d[0]), "+f"(d[1]), "+f"(d[2]), "+f"(d[3])
               : "r"(a[0]), "r"(a[1]), "r"(a[2]), "r"(a[3]), "r"(b[0]), "r"(b[1]));
}
__device__ __forceinline__ void mmaF16(uint32_t d[2], const uint32_t a[4], const uint32_t b[2]) {
  asm volatile("mma.sync.aligned.m16n8k16.row.col.f16.f16.f16.f16 "
               "{%0,%1}, {%2,%3,%4,%5}, {%6,%7}, {%0,%1};"
               : "+r"(d[0]), "+r"(d[1])
               : "r"(a[0]), "r"(a[1]), "r"(a[2]), "r"(a[3]), "r"(b[0]), "r"(b[1]));
}
__device__ __forceinline__ uint32_t hpack(float a, float b) {
  __half2 t = __floats2half2_rn(a, b);
  return *(uint32_t*)&t;
}
__device__ __forceinline__ float hlo(uint32_t v) { return __half2float(((__half2*)&v)->x); }
__device__ __forceinline__ float hhi(uint32_t v) { return __half2float(((__half2*)&v)->y); }

// ---------------- scratch (device globals; no allocations allowed) ----------------
#define NX (BATCH*DIM*HWX)
#define NP0 (BATCH*DIM*HW1)
#define NPF (BATCH*DIM*HWP)
#define NKV (BATCH*2*DIM*HWP)
#define WOFF_Q 0
#define WOFF_PL 65536
#define WOFF_KV 131072
#define WOFF_MIX 262144
#define NW 327680
__device__ fp16 g_xh[NX];
__device__ fp16 g_qh[NX];
__device__ fp16 g_mh[NX];
__device__ fp16 g_gf16[NX];
__device__ fp16 g_p0h[NP0];
__device__ fp16 g_pm16[NP0];
__device__ fp16 g_pfh[NPF];
__device__ fp16 g_kvh[NKV], g_kvl[NKV];
__device__ fp16 g_wh[NW],  g_wl[NW];

// ---------------- x -> fp16 hi ----------------
__global__ __launch_bounds__(256) void cvt_h_kernel(
    const float* __restrict__ s, fp16* __restrict__ h, int n4) {
  int i = blockIdx.x * 256 + threadIdx.x;
  if (i >= n4) return;
  float4 v = ((const float4*)s)[i];
  ((__half2*)h)[2*i]   = __floats2half2_rn(v.x, v.y);
  ((__half2*)h)[2*i+1] = __floats2half2_rn(v.z, v.w);
}
// ---------------- fused weight hi/lo split ----------------
__global__ __launch_bounds__(256) void cvt_w_kernel(
    const float* __restrict__ qw, const float* __restrict__ plw,
    const float* __restrict__ kvw, const float* __restrict__ mxw,
    fp16* __restrict__ h, fp16* __restrict__ l) {
  int i = blockIdx.x * 256 + threadIdx.x;
  if (i >= NW / 4) return;
  const float* src;
  int li;
  if (i < 16384)      { src = qw;  li = i; }
  else if (i < 32768) { src = plw; li = i - 16384; }
  else if (i < 65536) { src = kvw; li = i - 32768; }
  else                { src = mxw; li = i - 65536; }
  float4 v = ((const float4*)src)[li];
  __half2 h0 = __floats2half2_rn(v.x, v.y);
  __half2 h1 = __floats2half2_rn(v.z, v.w);
  __half2 l0 = __floats2half2_rn(v.x - __half2float(h0.x), v.y - __half2float(h0.y));
  __half2 l1 = __floats2half2_rn(v.z - __half2float(h1.x), v.w - __half2float(h1.y));
  ((__half2*)h)[2*i] = h0; ((__half2*)h)[2*i+1] = h1;
  ((__half2*)l)[2*i] = l0; ((__half2*)l)[2*i+1] = l1;
}

// ---------------- 1x1 conv: 2-pass split-fp16 HMMA, x4-trans B loads ----------------
#define CV_SMEM 49152

__global__ __launch_bounds__(256) void conv1x1_hf_kernel(
    const fp16* __restrict__ Ah, const fp16* __restrict__ Al,
    const fp16* __restrict__ Bh,
    const float* __restrict__ bias, float* __restrict__ Yf,
    fp16* __restrict__ Yh, fp16* __restrict__ Yl,
    int CO, int CI, int HW) {
  extern __shared__ __align__(1024) char smem[];
  char* sAh = smem;         char* sAl = smem + 16384;
  char* sBh = smem + 32768;
  uint32_t aAh = smem_u32(sAh), aAl = smem_u32(sAl);
  uint32_t aBh = smem_u32(sBh);
  int tid = threadIdx.x, lane = tid & 31, wid = tid >> 5;
  int m0 = blockIdx.y * 128, n0 = blockIdx.x * 128;
  const fp16* Bhb = Bh + (size_t)blockIdx.z * CI * HW;
  int mw = (wid & 3) * 32, nw = (wid >> 2) * 64;

  float acc[2][8][4];
  uint32_t accH[2][8][2];
#pragma unroll
  for (int i = 0; i < 2; i++)
#pragma unroll
    for (int j = 0; j < 8; j++) {
#pragma unroll
      for (int c = 0; c < 4; c++) acc[i][j][c] = 0.f;
      accH[i][j][0] = 0u; accH[i][j][1] = 0u;
    }

  for (int k0 = 0; k0 < CI; k0 += 64) {
#pragma unroll
    for (int i = 0; i < 4; i++) {
      int t = tid + i * 256;
      int m = t >> 3, kg = t & 7;
      size_t src = (size_t)(m0 + m) * CI + k0 + kg * 8;
      uint32_t dst = SW128(m * 128 + kg * 16);
      *(uint4*)(sAh + dst) = *(const uint4*)(Ah + src);
      *(uint4*)(sAl + dst) = *(const uint4*)(Al + src);
    }
#pragma unroll
    for (int i = 0; i < 4; i++) {
      int t = tid + i * 256;
      int k = t & 63, c = t >> 6;
      int gn = n0 + c * 8;
      uint4 vh;
      if (gn + 8 <= HW) {
        const char* ph = (const char*)(Bhb + (size_t)(k0 + k) * HW + gn);
        uint2 h0 = *(const uint2*)ph, h1 = *(const uint2*)(ph + 8);
        vh = make_uint4(h0.x, h0.y, h1.x, h1.y);
      } else {
        fp16 th[8];
#pragma unroll
        for (int j = 0; j < 8; j++) {
          int g = gn + j;
          th[j] = (g < HW) ? Bhb[(size_t)(k0 + k) * HW + g] : __float2half(0.f);
        }
        vh = *(uint4*)th;
      }
      *(uint4*)(sBh + (k * 256 + ((c ^ (k & 15)) << 4))) = vh;
    }
    __syncthreads();
#pragma unroll
    for (int s = 0; s < 4; s++) {
      uint32_t ah[2][4], al[2][4];
#pragma unroll
      for (int tm = 0; tm < 2; tm++) {
        uint32_t off = SW128((mw + tm * 16 + (lane & 15)) * 128 + s * 32 + (lane >> 4) * 16);
        ldm4(ah[tm], aAh + off);
        ldm4(al[tm], aAl + off);
      }
      int kk = s * 16 + (lane & 15);
#pragma unroll
      for (int ntp = 0; ntp < 4; ntp++) {
        int nt_eff = 2 * ntp + (lane >> 4);
        uint32_t cIdx = (uint32_t)(((nw >> 3) + nt_eff) ^ (kk & 15));
        uint32_t bq[4];
        ldm4t(bq, aBh + kk * 256 + (cIdx << 4));
#pragma unroll
        for (int tm = 0; tm < 2; tm++) {
          mmaF32(acc[tm][2*ntp],   ah[tm], bq);
          mmaF16(accH[tm][2*ntp],  al[tm], bq);
          mmaF32(acc[tm][2*ntp+1], ah[tm], bq + 2);
          mmaF16(accH[tm][2*ntp+1],al[tm], bq + 2);
        }
      }
    }
    __syncthreads();
  }
#pragma unroll
  for (int tm = 0; tm < 2; tm++) {
    int r0 = m0 + mw + tm * 16 + (lane >> 2);
    float b0 = bias[r0], b1 = bias[r0 + 8];
#pragma unroll
    for (int tn = 0; tn < 8; tn++) {
      int col = n0 + nw + tn * 8 + (lane & 3) * 2;
      if (col < HW) {
        float o0 = acc[tm][tn][0] + hlo(accH[tm][tn][0]) + b0;
        float o1 = acc[tm][tn][1] + hhi(accH[tm][tn][0]) + b0;
        float o2 = acc[tm][tn][2] + hlo(accH[tm][tn][1]) + b1;
        float o3 = acc[tm][tn][3] + hhi(accH[tm][tn][1]) + b1;
        size_t i0 = (size_t)blockIdx.z * CO * HW + (size_t)r0 * HW + col;
        size_t i1 = i0 + (size_t)8 * HW;
        if (Yf) {
          *(float2*)&Yf[i0] = make_float2(o0, o1);
          *(float2*)&Yf[i1] = make_float2(o2, o3);
        }
        if (Yh) {
          __half2 h0 = __floats2half2_rn(o0, o1);
          __half2 h1 = __floats2half2_rn(o2, o3);
          *(__half2*)&Yh[i0] = h0; *(__half2*)&Yh[i1] = h1;
          if (Yl) {
            __half2 l0 = __floats2half2_rn(o0 - __half2float(h0.x), o1 - __half2float(h0.y));
            __half2 l1 = __floats2half2_rn(o2 - __half2float(h1.x), o3 - __half2float(h1.y));
            *(__half2*)&Yl[i0] = l0; *(__half2*)&Yl[i1] = l1;
          }
        }
      }
    }
  }
}

// ---------------- dw1: 5x5 s2 + BN, fp32 in -> fp16, 4 outputs along y ----------------
// lane = x (coalesced); 11 input rows serve 4 stacked outputs.
__global__ __launch_bounds__(256) void dw1_y4_kernel(
    const float* __restrict__ X, const float* __restrict__ Wd,
    const float* __restrict__ bias, const float* __restrict__ gam,
    const float* __restrict__ bet, const float* __restrict__ mu,
    const float* __restrict__ var, fp16* __restrict__ Yh) {
  int idx = blockIdx.x * 256 + threadIdx.x;
  int total = BATCH * DIM * 7 * HP1;    // 7 y-groups of 4
  if (idx >= total) return;
  int x = idx % HP1; int t = idx / HP1;
  int yg = t % 7; t /= 7;
  int c = t % DIM; int b = t / DIM;
  int oy0 = yg * 4;
  const float* xp = X + (size_t)(b * DIM + c) * HWX;
  const float* wp = Wd + c * 25;
  float sums[4] = {0.f, 0.f, 0.f, 0.f};
#pragma unroll
  for (int rr = 0; rr < 11; rr++) {
    int iy = oy0 * 2 - 2 + rr;
    if (iy < 0 || iy >= HH) continue;
    const float* row = xp + iy * WW;
    float rv[5];
#pragma unroll
    for (int kx = 0; kx < 5; kx++) {
      int ix = x * 2 - 2 + kx;
      rv[kx] = (ix >= 0 && ix < WW) ? row[ix] : 0.f;
    }
#pragma unroll
    for (int o = 0; o < 4; o++) {
      int ky = rr - 2 * o;
      if (ky >= 0 && ky < 5) {
#pragma unroll
        for (int kx = 0; kx < 5; kx++) sums[o] += rv[kx] * wp[ky * 5 + kx];
      }
    }
  }
  float bsv = bias[c];
  float sc = gam[c] * rsqrtf(var[c] + BN_EPS);
  float muv = mu[c], bev = bet[c];
  size_t ob = ((size_t)(b * DIM + c) * HP1 + oy0) * HP1 + x;
#pragma unroll
  for (int o = 0; o < 4; o++)
    Yh[ob + (size_t)o * HP1] = __float2half_rn((sums[o] + bsv - muv) * sc + bev);
}

// ---------------- dw2: 5x5 s2 + BN, fp16 in -> fp16, 4 outputs along y (bounds) -------
__global__ __launch_bounds__(256) void dw2_y4_kernel(
    const fp16* __restrict__ X, const float* __restrict__ Wd,
    const float* __restrict__ bias, const float* __restrict__ gam,
    const float* __restrict__ bet, const float* __restrict__ mu,
    const float* __restrict__ var, fp16* __restrict__ Yh) {
  int idx = blockIdx.x * 256 + threadIdx.x;
  int total = BATCH * DIM * 4 * HP2;    // 4 y-groups of 4 (last partial: oy 12..13)
  if (idx >= total) return;
  int x = idx % HP2; int t = idx / HP2;
  int yg = t % 4; t /= 4;
  int c = t % DIM; int b = t / DIM;
  int oy0 = yg * 4;
  const fp16* xp = X + (size_t)(b * DIM + c) * HW1;
  const float* wp = Wd + c * 25;
  float sums[4] = {0.f, 0.f, 0.f, 0.f};
#pragma unroll
  for (int rr = 0; rr < 11; rr++) {
    int iy = oy0 * 2 - 2 + rr;
    if (iy < 0 || iy >= HP1) continue;
    const fp16* row = xp + iy * HP1;
    float rv[5];
#pragma unroll
    for (int kx = 0; kx < 5; kx++) {
      int ix = x * 2 - 2 + kx;
      rv[kx] = (ix >= 0 && ix < HP1) ? __half2float(row[ix]) : 0.f;
    }
#pragma unroll
    for (int o = 0; o < 4; o++) {
      int ky = rr - 2 * o;
      if (ky >= 0 && ky < 5) {
#pragma unroll
        for (int kx = 0; kx < 5; kx++) sums[o] += rv[kx] * wp[ky * 5 + kx];
      }
    }
  }
  float bsv = bias[c];
  float sc = gam[c] * rsqrtf(var[c] + BN_EPS);
  float muv = mu[c], bev = bet[c];
  size_t ob = ((size_t)(b * DIM + c) * HP2 + oy0) * HP2 + x;
#pragma unroll
  for (int o = 0; o < 4; o++)
    if (oy0 + o < HP2)
      Yh[ob + (size_t)o * HP2] = __float2half_rn((sums[o] + bsv - muv) * sc + bev);
}

// ---------------- gate: dw5x5 s1 + SiLU + sigmoid-gate, 4 outputs along y -------------
__global__ __launch_bounds__(256) void gate_y4_kernel(
    const fp16* __restrict__ Q, const float* __restrict__ Wd,
    const float* __restrict__ bias, const fp16* __restrict__ G,
    fp16* __restrict__ Oh) {
  int idx = blockIdx.x * 256 + threadIdx.x;
  int total = BATCH * DIM * 14 * WW;    // 14 y-groups of 4
  if (idx >= total) return;
  int x = idx % WW; int t = idx / WW;
  int yg = t % 14; t /= 14;
  int c = t % DIM; int b = t / DIM;
  int oy0 = yg * 4;
  const fp16* xp = Q + (size_t)(b * DIM + c) * HWX;
  const float* wp = Wd + c * 25;
  float sums[4] = {0.f, 0.f, 0.f, 0.f};
#pragma unroll
  for (int rr = 0; rr < 8; rr++) {
    int iy = oy0 - 2 + rr;
    if (iy < 0 || iy >= HH) continue;
    const fp16* row = xp + iy * WW;
    float rv[5];
#pragma unroll
    for (int kx = 0; kx < 5; kx++) {
      int ix = x - 2 + kx;
      rv[kx] = (ix >= 0 && ix < WW) ? __half2float(row[ix]) : 0.f;
    }
#pragma unroll
    for (int o = 0; o < 4; o++) {
      int ky = rr - o;
      if (ky >= 0 && ky < 5) {
#pragma unroll
        for (int kx = 0; kx < 5; kx++) sums[o] += rv[kx] * wp[ky * 5 + kx];
      }
    }
  }
  float bsv = bias[c];
  size_t ob = (size_t)(b * DIM + c) * HWX + (size_t)oy0 * WW + x;
#pragma unroll
  for (int o = 0; o < 4; o++) {
    float s = sums[o] + bsv;
    float lf = s / (1.f + __expf(-s));
    float gv = __half2float(G[ob + (size_t)o * WW]);
    float sg = 1.f / (1.f + __expf(-gv));
    Oh[ob + (size_t)o * WW] = __float2half_rn(lf * sg * gv);
  }
}

// ---------------- attention v7: x4 B-loads, no max-pass, fp16 output ----------------
#define A6_AQH 0
#define A6_KH  8704
#define A6_KL  26624
#define A6_VH  44544
#define A6_VL  59392
#define A6_BYTES 74240

__global__ __launch_bounds__(128, 2) void attn7_kernel(
    const fp16* __restrict__ Qh,
    const fp16* __restrict__ KVh, const fp16* __restrict__ KVl,
    fp16* __restrict__ GF) {
  extern __shared__ __align__(1024) char sm[];
  uint32_t sb = smem_u32(sm);
  int tid = threadIdx.x, lane = tid & 31, warp = tid >> 5;
  int part = blockIdx.x % 7;
  int bh = blockIdx.x / 7;
  int b = bh >> 3, h = bh & 7;
  const fp16* kHh = KVh + ((size_t)b * 2 * DIM + h * 32) * HWP;
  const fp16* kHl = KVl + ((size_t)b * 2 * DIM + h * 32) * HWP;
  const fp16* vHh = kHh + (size_t)DIM * HWP;
  const fp16* vHl = kHl + (size_t)DIM * HWP;
  const float scal = 0.17677669529663687f;  // 32^-0.5

  for (int t = tid; t < 896; t += 128) {
    int d = t & 31, jg = t >> 5;
    int j0 = jg * 8;
    fp16 th[8], tl[8], uh[8], ul[8];
    if (j0 + 8 <= HWP) {
      const char* pkh = (const char*)(kHh + (size_t)d * HWP + j0);
      const char* pkl = (const char*)(kHl + (size_t)d * HWP + j0);
      const char* pvh = (const char*)(vHh + (size_t)d * HWP + j0);
      const char* pvl = (const char*)(vHl + (size_t)d * HWP + j0);
      *(uint2*)th = *(const uint2*)pkh; *(uint2*)(th + 4) = *(const uint2*)(pkh + 8);
      *(uint2*)tl = *(const uint2*)pkl; *(uint2*)(tl + 4) = *(const uint2*)(pkl + 8);
      *(uint2*)uh = *(const uint2*)pvh; *(uint2*)(uh + 4) = *(const uint2*)(pvh + 8);
      *(uint2*)ul = *(const uint2*)pvl; *(uint2*)(ul + 4) = *(const uint2*)(pvl + 8);
    } else {
      fp16 z = __float2half(0.f);
#pragma unroll
      for (int j = 0; j < 8; j++) {
        int g = j0 + j;
        bool v = g < HWP;
        th[j] = v ? kHh[(size_t)d * HWP + g] : z;
        tl[j] = v ? kHl[(size_t)d * HWP + g] : z;
        uh[j] = v ? vHh[(size_t)d * HWP + g] : z;
        ul[j] = v ? vHl[(size_t)d * HWP + g] : z;
      }
    }
#pragma unroll
    for (int j = 0; j < 8; j++) {
      *(fp16*)(sm + A6_KH + ((j0 + j) * 40 + d) * 2) = th[j];
      *(fp16*)(sm + A6_KL + ((j0 + j) * 40 + d) * 2) = tl[j];
    }
    *(uint4*)(sm + A6_VH + (d * 232 + j0) * 2) = *(uint4*)uh;
    *(uint4*)(sm + A6_VL + (d * 232 + j0) * 2) = *(uint4*)ul;
  }

  const fp16* qbh = Qh + ((size_t)b * DIM + h * 32) * HWX;
  fp16* GFb = GF + ((size_t)b * DIM + h * 32) * HWX;
  int mw = warp * 16;

  for (int it = 0; it < 7; it++) {
    int q0 = (part * 7 + it) * 64;
    __syncthreads();
    for (int t = tid; t < 256; t += 128) {
      int d = t & 31, mg = t >> 5;
      uint4 vh = *(const uint4*)(qbh + (size_t)d * HWX + q0 + mg * 8);
      fp16* eh = (fp16*)&vh;
#pragma unroll
      for (int j = 0; j < 8; j++)
        *(fp16*)(sm + A6_AQH + ((mg * 8 + j) * 40 + d) * 2) = eh[j];
    }
    __syncthreads();

    float acc[26][4];
    uint32_t accH[26][2];
#pragma unroll
    for (int nt = 0; nt < 26; nt++) {
#pragma unroll
      for (int c = 0; c < 4; c++) acc[nt][c] = 0.f;
      accH[nt][0] = 0u; accH[nt][1] = 0u;
    }
    int rn = ((lane >> 4) << 3) + (lane & 7);
    uint32_t kb = ((lane >> 3) & 1) * 16;
#pragma unroll
    for (int s = 0; s < 2; s++) {
      uint32_t ah[4];
      uint32_t aoff = ((mw + (lane & 15)) * 40 + s * 16) * 2 + (lane >> 4) * 16;
      ldm4(ah, sb + A6_AQH + aoff);
#pragma unroll
      for (int np = 0; np < 13; np++) {
        uint32_t boff = (uint32_t)(((np * 16 + rn) * 40 + s * 16) * 2) + kb;
        uint32_t bh4[4], bl4[4];
        ldm4(bh4, sb + A6_KH + boff);
        ldm4(bl4, sb + A6_KL + boff);
        mmaF32(acc[2*np],   ah, bh4);
        mmaF16(accH[2*np],  ah, bl4);
        mmaF32(acc[2*np+1], ah, bh4 + 2);
        mmaF16(accH[2*np+1],ah, bl4 + 2);
      }
    }

    float sum1 = 0.f, sum2 = 0.f;
#pragma unroll
    for (int nt = 0; nt < 26; nt++) {
      int jb = nt * 8 + (lane & 3) * 2;
      float e0 = (acc[nt][0] + hlo(accH[nt][0])) * scal;
      float e1 = (acc[nt][1] + hhi(accH[nt][0])) * scal;
      float e2 = (acc[nt][2] + hlo(accH[nt][1])) * scal;
      float e3 = (acc[nt][3] + hhi(accH[nt][1])) * scal;
      e0 = (jb < HWP)     ? __expf(e0) : 0.f;
      e1 = (jb + 1 < HWP) ? __expf(e1) : 0.f;
      e2 = (jb < HWP)     ? __expf(e2) : 0.f;
      e3 = (jb + 1 < HWP) ? __expf(e3) : 0.f;
      acc[nt][0] = e0; acc[nt][1] = e1; acc[nt][2] = e2; acc[nt][3] = e3;
      sum1 += e0 + e1;
      sum2 += e2 + e3;
    }
#pragma unroll
    for (int o = 1; o <= 2; o <<= 1) {
      sum1 += __shfl_xor_sync(0xffffffffu, sum1, o);
      sum2 += __shfl_xor_sync(0xffffffffu, sum2, o);
    }
    float rec1 = 1.f / sum1, rec2 = 1.f / sum2;

    float acc2[4][4];
    uint32_t acc2H[4][2];
#pragma unroll
    for (int nt = 0; nt < 4; nt++) {
#pragma unroll
      for (int c = 0; c < 4; c++) acc2[nt][c] = 0.f;
      acc2H[nt][0] = 0u; acc2H[nt][1] = 0u;
    }
#pragma unroll 1
    for (int k = 0; k < 13; k++) {
      uint32_t ph[4];
      ph[0] = hpack(acc[2*k][0] * rec1,   acc[2*k][1] * rec1);
      ph[1] = hpack(acc[2*k][2] * rec2,   acc[2*k][3] * rec2);
      ph[2] = hpack(acc[2*k+1][0] * rec1, acc[2*k+1][1] * rec1);
      ph[3] = hpack(acc[2*k+1][2] * rec2, acc[2*k+1][3] * rec2);
#pragma unroll
      for (int np = 0; np < 2; np++) {
        uint32_t boff = (uint32_t)(((np * 16 + rn) * 232 + k * 16) * 2) + kb;
        uint32_t vh4[4], vl4[4];
        ldm4(vh4, sb + A6_VH + boff);
        ldm4(vl4, sb + A6_VL + boff);
        mmaF32(acc2[2*np],   ph, vh4);
        mmaF16(acc2H[2*np],  ph, vl4);
        mmaF32(acc2[2*np+1], ph, vh4 + 2);
        mmaF16(acc2H[2*np+1],ph, vl4 + 2);
      }
    }
    __syncthreads();

    float* Ob = (float*)sm;
    {
      int m1 = mw + (lane >> 2), m2 = m1 + 8;
      int cb = (lane & 3) * 2;
#pragma unroll
      for (int nt = 0; nt < 4; nt++) {
        int dcol = nt * 8 + cb;
        Ob[dcol * 68 + m1]       = acc2[nt][0] + hlo(acc2H[nt][0]);
        Ob[(dcol + 1) * 68 + m1] = acc2[nt][1] + hhi(acc2H[nt][0]);
        Ob[dcol * 68 + m2]       = acc2[nt][2] + hlo(acc2H[nt][1]);
        Ob[(dcol + 1) * 68 + m2] = acc2[nt][3] + hhi(acc2H[nt][1]);
      }
    }
    __syncthreads();
    {
      int row = tid >> 2, i0 = (tid & 3) * 16;
#pragma unroll
      for (int c = 0; c < 4; c++) {
        int i = i0 + c * 4;
        float4 v = *(float4*)&Ob[row * 68 + i];
        __half2 p0 = __floats2half2_rn(v.x, v.y);
        __half2 p1 = __floats2half2_rn(v.z, v.w);
        uint2 pk = make_uint2(*(uint32_t*)&p0, *(uint32_t*)&p1);
        *(uint2*)&GFb[(size_t)row * HWX + q0 + i] = pk;
      }
    }
  }
}

extern "C" void kernel_launch(void* const* d_in, const int* in_sizes, int n_in,
                              void* d_out, int out_size) {
  const float* x     = (const float*)d_in[0];
  const float* q_w   = (const float*)d_in[1];
  const float* q_b   = (const float*)d_in[2];
  const float* kv_w  = (const float*)d_in[3];
  const float* kv_b  = (const float*)d_in[4];
  const float* p0_w  = (const float*)d_in[5];
  const float* p0_b  = (const float*)d_in[6];
  const float* bn0_g = (const float*)d_in[7];
  const float* bn0_b = (const float*)d_in[8];
  const float* bn0_m = (const float*)d_in[9];
  const float* bn0_v = (const float*)d_in[10];
  const float* pl0_w = (const float*)d_in[11];
  const float* pl0_b = (const float*)d_in[12];
  const float* p1_w  = (const float*)d_in[13];
  const float* p1_b  = (const float*)d_in[14];
  const float* bn1_g = (const float*)d_in[15];
  const float* bn1_b = (const float*)d_in[16];
  const float* bn1_m = (const float*)d_in[17];
  const float* bn1_v = (const float*)d_in[18];
  const float* loc_w = (const float*)d_in[19];
  const float* loc_b = (const float*)d_in[20];
  const float* mix_w = (const float*)d_in[21];
  const float* mix_b = (const float*)d_in[22];
  float* out = (float*)d_out;

  fp16 *xh, *qh, *mh, *gf16, *p0h, *pm16, *pfh, *kvh, *kvl, *wh, *wl;
  cudaGetSymbolAddress((void**)&xh, g_xh);
  cudaGetSymbolAddress((void**)&qh, g_qh);
  cudaGetSymbolAddress((void**)&mh, g_mh);
  cudaGetSymbolAddress((void**)&gf16, g_gf16);
  cudaGetSymbolAddress((void**)&p0h, g_p0h);
  cudaGetSymbolAddress((void**)&pm16, g_pm16);
  cudaGetSymbolAddress((void**)&pfh, g_pfh);
  cudaGetSymbolAddress((void**)&kvh, g_kvh); cudaGetSymbolAddress((void**)&kvl, g_kvl);
  cudaGetSymbolAddress((void**)&wh, g_wh);   cudaGetSymbolAddress((void**)&wl, g_wl);

  cudaFuncSetAttribute(conv1x1_hf_kernel, cudaFuncAttributeMaxDynamicSharedMemorySize, CV_SMEM);
  cudaFuncSetAttribute(attn7_kernel, cudaFuncAttributeMaxDynamicSharedMemorySize, A6_BYTES);

  // 0. pre-split: all weights in one launch; x hi
  cvt_h_kernel<<<(NX/4 + 255)/256, 256>>>(x, xh, NX/4);
  cvt_w_kernel<<<(NW/4 + 255)/256, 256>>>(q_w, pl0_w, kv_w, mix_w, wh, wl);

  // 1. q_local -> fp16 hi (attention Q + gate input)
  conv1x1_hf_kernel<<<dim3((HWX + 127)/128, DIM/128, BATCH), 256, CV_SMEM>>>(
      wh + WOFF_Q, wl + WOFF_Q, xh, q_b, (float*)nullptr, qh, (fp16*)nullptr, DIM, DIM, HWX);
  // 2. p0 = BN0(dw5x5_s2(x)) -> fp16  (vertical 4-wide, coalesced lanes)
  dw1_y4_kernel<<<(BATCH*DIM*7*HP1 + 255)/256, 256>>>(
      x, p0_w, p0_b, bn0_g, bn0_b, bn0_m, bn0_v, p0h);
  // 3. pmid = conv1x1(p0) -> fp16
  conv1x1_hf_kernel<<<dim3((HW1 + 127)/128, DIM/128, BATCH), 256, CV_SMEM>>>(
      wh + WOFF_PL, wl + WOFF_PL, p0h, pl0_b, (float*)nullptr, pm16, (fp16*)nullptr, DIM, DIM, HW1);
  // 4. pfin = BN1(dw5x5_s2(pmid)) -> fp16 (vertical 4-wide)
  dw2_y4_kernel<<<(BATCH*DIM*4*HP2 + 255)/256, 256>>>(
      pm16, p1_w, p1_b, bn1_g, bn1_b, bn1_m, bn1_v, pfh);
  // 5. kv = conv1x1(pfin) -> fp16 hi/lo
  conv1x1_hf_kernel<<<dim3((HWP + 127)/128, (2*DIM)/128, BATCH), 256, CV_SMEM>>>(
      wh + WOFF_KV, wl + WOFF_KV, pfh, kv_b, (float*)nullptr, kvh, kvl, 2*DIM, DIM, HWP);
  // 6. attention -> gf16
  attn7_kernel<<<BATCH*HEADS*7, 128, A6_BYTES>>>(qh, kvh, kvl, gf16);
  // 7. local mixer + gating (vertical 4-wide) -> mh
  gate_y4_kernel<<<(BATCH*DIM*14*WW + 255)/256, 256>>>(qh, loc_w, loc_b, gf16, mh);
  // 8. out = conv1x1(mixbuf) -> f32
  conv1x1_hf_kernel<<<dim3((HWX + 127)/128, DIM/128, BATCH), 256, CV_SMEM>>>(
      wh + WOFF_MIX, wl + WOFF_MIX, mh, mix_b, out, (fp16*)nullptr, (fp16*)nullptr, DIM, DIM, HWX);
}

// round 16
// speedup vs baseline: 1.7100x; 1.0183x over previous
#include <cuda_runtime.h>
#include <cuda_fp16.h>
#include <cstdint>

#define BATCH 16
#define DIM 256
#define HH 56
#define WW 56
#define HWX (HH*WW)          // 3136
#define HEADS 8
#define DH 32
#define HP1 28
#define HW1 (HP1*HP1)        // 784
#define HP2 14
#define HWP (HP2*HP2)        // 196
#define BN_EPS 1e-5f

#define SW128(x) ((x) ^ (((x) >> 3) & 0x70))

typedef __half fp16;

__device__ __forceinline__ uint32_t smem_u32(const void* p) {
  uint32_t a;
  asm("{ .reg .u64 t; cvta.to.shared.u64 t, %1; cvt.u32.u64 %0, t; }" : "=r"(a) : "l"(p));
  return a;
}
__device__ __forceinline__ void ldm4(uint32_t a[4], uint32_t addr) {
  asm volatile("ldmatrix.sync.aligned.m8n8.x4.shared.b16 {%0,%1,%2,%3}, [%4];"
               : "=r"(a[0]), "=r"(a[1]), "=r"(a[2]), "=r"(a[3]) : "r"(addr));
}
__device__ __forceinline__ void ldm4t(uint32_t a[4], uint32_t addr) {
  asm volatile("ldmatrix.sync.aligned.m8n8.x4.trans.shared.b16 {%0,%1,%2,%3}, [%4];"
               : "=r"(a[0]), "=r"(a[1]), "=r"(a[2]), "=r"(a[3]) : "r"(addr));
}
__device__ __forceinline__ void mmaF32(float d[4], const uint32_t a[4], const uint32_t b[2]) {
  asm volatile("mma.sync.aligned.m16n8k16.row.col.f32.f16.f16.f32 "
               "{%0,%1,%2,%3}, {%4,%5,%6,%7}, {%8,%9}, {%0,%1,%2,%3};"
               : "+f"(d[0]), "+f"(d[1]), "+f"(d[2]), "+f"(d[3])
               : "r"(a[0]), "r"(a[1]), "r"(a[2]), "r"(a[3]), "r"(b[0]), "r"(b[1]));
}
__device__ __forceinline__ void mmaF16(uint32_t d[2], const uint32_t a[4], const uint32_t b[2]) {
  asm volatile("mma.sync.aligned.m16n8k16.row.col.f16.f16.f16.f16 "
               "{%0,%1}, {%2,%3,%4,%5}, {%6,%7}, {%0,%1};"
               : "+r"(d[0]), "+r"(d[1])
               : "r"(a[0]), "r"(a[1]), "r"(a[2]), "r"(a[3]), "r"(b[0]), "r"(b[1]));
}
__device__ __forceinline__ uint32_t hpack(float a, float b) {
  __half2 t = __floats2half2_rn(a, b);
  return *(uint32_t*)&t;
}
__device__ __forceinline__ float hlo(uint32_t v) { return __half2float(((__half2*)&v)->x); }
__device__ __forceinline__ float hhi(uint32_t v) { return __half2float(((__half2*)&v)->y); }

// ---------------- scratch (device globals; no allocations allowed) ----------------
#define NX (BATCH*DIM*HWX)
#define NP0 (BATCH*DIM*HW1)
#define NPF (BATCH*DIM*HWP)
#define NKV (BATCH*2*DIM*HWP)
#define WOFF_Q 0
#define WOFF_PL 65536
#define WOFF_KV 131072
#define WOFF_MIX 262144
#define NW 327680
__device__ fp16 g_xh[NX];
__device__ fp16 g_qh[NX];
__device__ fp16 g_mh[NX];
__device__ fp16 g_gf16[NX];
__device__ fp16 g_p0h[NP0];
__device__ fp16 g_pm16[NP0];
__device__ fp16 g_pfh[NPF];
__device__ fp16 g_kvh[NKV], g_kvl[NKV];
__device__ fp16 g_wh[NW],  g_wl[NW];

// ---------------- x -> fp16 hi ----------------
__global__ __launch_bounds__(256) void cvt_h_kernel(
    const float* __restrict__ s, fp16* __restrict__ h, int n4) {
  int i = blockIdx.x * 256 + threadIdx.x;
  if (i >= n4) return;
  float4 v = ((const float4*)s)[i];
  ((__half2*)h)[2*i]   = __floats2half2_rn(v.x, v.y);
  ((__half2*)h)[2*i+1] = __floats2half2_rn(v.z, v.w);
}
// ---------------- fused weight hi/lo split ----------------
__global__ __launch_bounds__(256) void cvt_w_kernel(
    const float* __restrict__ qw, const float* __restrict__ plw,
    const float* __restrict__ kvw, const float* __restrict__ mxw,
    fp16* __restrict__ h, fp16* __restrict__ l) {
  int i = blockIdx.x * 256 + threadIdx.x;
  if (i >= NW / 4) return;
  const float* src;
  int li;
  if (i < 16384)      { src = qw;  li = i; }
  else if (i < 32768) { src = plw; li = i - 16384; }
  else if (i < 65536) { src = kvw; li = i - 32768; }
  else                { src = mxw; li = i - 65536; }
  float4 v = ((const float4*)src)[li];
  __half2 h0 = __floats2half2_rn(v.x, v.y);
  __half2 h1 = __floats2half2_rn(v.z, v.w);
  __half2 l0 = __floats2half2_rn(v.x - __half2float(h0.x), v.y - __half2float(h0.y));
  __half2 l1 = __floats2half2_rn(v.z - __half2float(h1.x), v.w - __half2float(h1.y));
  ((__half2*)h)[2*i] = h0; ((__half2*)h)[2*i+1] = h1;
  ((__half2*)l)[2*i] = l0; ((__half2*)l)[2*i+1] = l1;
}

// ---------------- 1x1 conv: 2-pass split-fp16 HMMA, x4-trans B loads ----------------
#define CV_SMEM 49152

__global__ __launch_bounds__(256) void conv1x1_hf_kernel(
    const fp16* __restrict__ Ah, const fp16* __restrict__ Al,
    const fp16* __restrict__ Bh,
    const float* __restrict__ bias, float* __restrict__ Yf,
    fp16* __restrict__ Yh, fp16* __restrict__ Yl,
    int CO, int CI, int HW) {
  extern __shared__ __align__(1024) char smem[];
  char* sAh = smem;         char* sAl = smem + 16384;
  char* sBh = smem + 32768;
  uint32_t aAh = smem_u32(sAh), aAl = smem_u32(sAl);
  uint32_t aBh = smem_u32(sBh);
  int tid = threadIdx.x, lane = tid & 31, wid = tid >> 5;
  int m0 = blockIdx.y * 128, n0 = blockIdx.x * 128;
  const fp16* Bhb = Bh + (size_t)blockIdx.z * CI * HW;
  int mw = (wid & 3) * 32, nw = (wid >> 2) * 64;

  float acc[2][8][4];
  uint32_t accH[2][8][2];
#pragma unroll
  for (int i = 0; i < 2; i++)
#pragma unroll
    for (int j = 0; j < 8; j++) {
#pragma unroll
      for (int c = 0; c < 4; c++) acc[i][j][c] = 0.f;
      accH[i][j][0] = 0u; accH[i][j][1] = 0u;
    }

  for (int k0 = 0; k0 < CI; k0 += 64) {
#pragma unroll
    for (int i = 0; i < 4; i++) {
      int t = tid + i * 256;
      int m = t >> 3, kg = t & 7;
      size_t src = (size_t)(m0 + m) * CI + k0 + kg * 8;
      uint32_t dst = SW128(m * 128 + kg * 16);
      *(uint4*)(sAh + dst) = *(const uint4*)(Ah + src);
      *(uint4*)(sAl + dst) = *(const uint4*)(Al + src);
    }
#pragma unroll
    for (int i = 0; i < 4; i++) {
      int t = tid + i * 256;
      int k = t & 63, c = t >> 6;
      int gn = n0 + c * 8;
      uint4 vh;
      if (gn + 8 <= HW) {
        const char* ph = (const char*)(Bhb + (size_t)(k0 + k) * HW + gn);
        uint2 h0 = *(const uint2*)ph, h1 = *(const uint2*)(ph + 8);
        vh = make_uint4(h0.x, h0.y, h1.x, h1.y);
      } else {
        fp16 th[8];
#pragma unroll
        for (int j = 0; j < 8; j++) {
          int g = gn + j;
          th[j] = (g < HW) ? Bhb[(size_t)(k0 + k) * HW + g] : __float2half(0.f);
        }
        vh = *(uint4*)th;
      }
      *(uint4*)(sBh + (k * 256 + ((c ^ (k & 15)) << 4))) = vh;
    }
    __syncthreads();
#pragma unroll
    for (int s = 0; s < 4; s++) {
      uint32_t ah[2][4], al[2][4];
#pragma unroll
      for (int tm = 0; tm < 2; tm++) {
        uint32_t off = SW128((mw + tm * 16 + (lane & 15)) * 128 + s * 32 + (lane >> 4) * 16);
        ldm4(ah[tm], aAh + off);
        ldm4(al[tm], aAl + off);
      }
      int kk = s * 16 + (lane & 15);
#pragma unroll
      for (int ntp = 0; ntp < 4; ntp++) {
        int nt_eff = 2 * ntp + (lane >> 4);
        uint32_t cIdx = (uint32_t)(((nw >> 3) + nt_eff) ^ (kk & 15));
        uint32_t bq[4];
        ldm4t(bq, aBh + kk * 256 + (cIdx << 4));
#pragma unroll
        for (int tm = 0; tm < 2; tm++) {
          mmaF32(acc[tm][2*ntp],   ah[tm], bq);
          mmaF16(accH[tm][2*ntp],  al[tm], bq);
          mmaF32(acc[tm][2*ntp+1], ah[tm], bq + 2);
          mmaF16(accH[tm][2*ntp+1],al[tm], bq + 2);
        }
      }
    }
    __syncthreads();
  }
#pragma unroll
  for (int tm = 0; tm < 2; tm++) {
    int r0 = m0 + mw + tm * 16 + (lane >> 2);
    float b0 = bias[r0], b1 = bias[r0 + 8];
#pragma unroll
    for (int tn = 0; tn < 8; tn++) {
      int col = n0 + nw + tn * 8 + (lane & 3) * 2;
      if (col < HW) {
        float o0 = acc[tm][tn][0] + hlo(accH[tm][tn][0]) + b0;
        float o1 = acc[tm][tn][1] + hhi(accH[tm][tn][0]) + b0;
        float o2 = acc[tm][tn][2] + hlo(accH[tm][tn][1]) + b1;
        float o3 = acc[tm][tn][3] + hhi(accH[tm][tn][1]) + b1;
        size_t i0 = (size_t)blockIdx.z * CO * HW + (size_t)r0 * HW + col;
        size_t i1 = i0 + (size_t)8 * HW;
        if (Yf) {
          *(float2*)&Yf[i0] = make_float2(o0, o1);
          *(float2*)&Yf[i1] = make_float2(o2, o3);
        }
        if (Yh) {
          __half2 h0 = __floats2half2_rn(o0, o1);
          __half2 h1 = __floats2half2_rn(o2, o3);
          *(__half2*)&Yh[i0] = h0; *(__half2*)&Yh[i1] = h1;
          if (Yl) {
            __half2 l0 = __floats2half2_rn(o0 - __half2float(h0.x), o1 - __half2float(h0.y));
            __half2 l1 = __floats2half2_rn(o2 - __half2float(h1.x), o3 - __half2float(h1.y));
            *(__half2*)&Yl[i0] = l0; *(__half2*)&Yl[i1] = l1;
          }
        }
      }
    }
  }
}

// ---------------- dw1: 5x5 s2 + BN, fp16 in -> fp16, 4 outputs along y ----------------
__global__ __launch_bounds__(256) void dw1h_y4_kernel(
    const fp16* __restrict__ X, const float* __restrict__ Wd,
    const float* __restrict__ bias, const float* __restrict__ gam,
    const float* __restrict__ bet, const float* __restrict__ mu,
    const float* __restrict__ var, fp16* __restrict__ Yh) {
  int idx = blockIdx.x * 256 + threadIdx.x;
  int total = BATCH * DIM * 7 * HP1;    // 7 y-groups of 4
  if (idx >= total) return;
  int x = idx % HP1; int t = idx / HP1;
  int yg = t % 7; t /= 7;
  int c = t % DIM; int b = t / DIM;
  int oy0 = yg * 4;
  const fp16* xp = X + (size_t)(b * DIM + c) * HWX;
  const float* wp = Wd + c * 25;
  float sums[4] = {0.f, 0.f, 0.f, 0.f};
#pragma unroll
  for (int rr = 0; rr < 11; rr++) {
    int iy = oy0 * 2 - 2 + rr;
    if (iy < 0 || iy >= HH) continue;
    const fp16* row = xp + iy * WW;
    float rv[5];
#pragma unroll
    for (int kx = 0; kx < 5; kx++) {
      int ix = x * 2 - 2 + kx;
      rv[kx] = (ix >= 0 && ix < WW) ? __half2float(row[ix]) : 0.f;
    }
#pragma unroll
    for (int o = 0; o < 4; o++) {
      int ky = rr - 2 * o;
      if (ky >= 0 && ky < 5) {
#pragma unroll
        for (int kx = 0; kx < 5; kx++) sums[o] += rv[kx] * wp[ky * 5 + kx];
      }
    }
  }
  float bsv = bias[c];
  float sc = gam[c] * rsqrtf(var[c] + BN_EPS);
  float muv = mu[c], bev = bet[c];
  size_t ob = ((size_t)(b * DIM + c) * HP1 + oy0) * HP1 + x;
#pragma unroll
  for (int o = 0; o < 4; o++)
    Yh[ob + (size_t)o * HP1] = __float2half_rn((sums[o] + bsv - muv) * sc + bev);
}

// ---------------- dw2: 5x5 s2 + BN, fp16 in -> fp16, 4 outputs along y (bounds) -------
__global__ __launch_bounds__(256) void dw2_y4_kernel(
    const fp16* __restrict__ X, const float* __restrict__ Wd,
    const float* __restrict__ bias, const float* __restrict__ gam,
    const float* __restrict__ bet, const float* __restrict__ mu,
    const float* __restrict__ var, fp16* __restrict__ Yh) {
  int idx = blockIdx.x * 256 + threadIdx.x;
  int total = BATCH * DIM * 4 * HP2;
  if (idx >= total) return;
  int x = idx % HP2; int t = idx / HP2;
  int yg = t % 4; t /= 4;
  int c = t % DIM; int b = t / DIM;
  int oy0 = yg * 4;
  const fp16* xp = X + (size_t)(b * DIM + c) * HW1;
  const float* wp = Wd + c * 25;
  float sums[4] = {0.f, 0.f, 0.f, 0.f};
#pragma unroll
  for (int rr = 0; rr < 11; rr++) {
    int iy = oy0 * 2 - 2 + rr;
    if (iy < 0 || iy >= HP1) continue;
    const fp16* row = xp + iy * HP1;
    float rv[5];
#pragma unroll
    for (int kx = 0; kx < 5; kx++) {
      int ix = x * 2 - 2 + kx;
      rv[kx] = (ix >= 0 && ix < HP1) ? __half2float(row[ix]) : 0.f;
    }
#pragma unroll
    for (int o = 0; o < 4; o++) {
      int ky = rr - 2 * o;
      if (ky >= 0 && ky < 5) {
#pragma unroll
        for (int kx = 0; kx < 5; kx++) sums[o] += rv[kx] * wp[ky * 5 + kx];
      }
    }
  }
  float bsv = bias[c];
  float sc = gam[c] * rsqrtf(var[c] + BN_EPS);
  float muv = mu[c], bev = bet[c];
  size_t ob = ((size_t)(b * DIM + c) * HP2 + oy0) * HP2 + x;
#pragma unroll
  for (int o = 0; o < 4; o++)
    if (oy0 + o < HP2)
      Yh[ob + (size_t)o * HP2] = __float2half_rn((sums[o] + bsv - muv) * sc + bev);
}

// ---------------- gate: dw5x5 s1 + SiLU + sigmoid-gate, 4 outputs along y -------------
__global__ __launch_bounds__(256) void gate_y4_kernel(
    const fp16* __restrict__ Q, const float* __restrict__ Wd,
    const float* __restrict__ bias, const fp16* __restrict__ G,
    fp16* __restrict__ Oh) {
  int idx = blockIdx.x * 256 + threadIdx.x;
  int total = BATCH * DIM * 14 * WW;
  if (idx >= total) return;
  int x = idx % WW; int t = idx / WW;
  int yg = t % 14; t /= 14;
  int c = t % DIM; int b = t / DIM;
  int oy0 = yg * 4;
  const fp16* xp = Q + (size_t)(b * DIM + c) * HWX;
  const float* wp = Wd + c * 25;
  float sums[4] = {0.f, 0.f, 0.f, 0.f};
#pragma unroll
  for (int rr = 0; rr < 8; rr++) {
    int iy = oy0 - 2 + rr;
    if (iy < 0 || iy >= HH) continue;
    const fp16* row = xp + iy * WW;
    float rv[5];
#pragma unroll
    for (int kx = 0; kx < 5; kx++) {
      int ix = x - 2 + kx;
      rv[kx] = (ix >= 0 && ix < WW) ? __half2float(row[ix]) : 0.f;
    }
#pragma unroll
    for (int o = 0; o < 4; o++) {
      int ky = rr - o;
      if (ky >= 0 && ky < 5) {
#pragma unroll
        for (int kx = 0; kx < 5; kx++) sums[o] += rv[kx] * wp[ky * 5 + kx];
      }
    }
  }
  float bsv = bias[c];
  size_t ob = (size_t)(b * DIM + c) * HWX + (size_t)oy0 * WW + x;
#pragma unroll
  for (int o = 0; o < 4; o++) {
    float s = sums[o] + bsv;
    float lf = s / (1.f + __expf(-s));
    float gv = __half2float(G[ob + (size_t)o * WW]);
    float sg = 1.f / (1.f + __expf(-gv));
    Oh[ob + (size_t)o * WW] = __float2half_rn(lf * sg * gv);
  }
}

// ---------------- attention v7: x4 B-loads, no max-pass, fp16 output, 3 CTA/SM --------
#define A6_AQH 0
#define A6_KH  8704
#define A6_KL  26624
#define A6_VH  44544
#define A6_VL  59392
#define A6_BYTES 74240

__global__ __launch_bounds__(128, 3) void attn7_kernel(
    const fp16* __restrict__ Qh,
    const fp16* __restrict__ KVh, const fp16* __restrict__ KVl,
    fp16* __restrict__ GF) {
  extern __shared__ __align__(1024) char sm[];
  uint32_t sb = smem_u32(sm);
  int tid = threadIdx.x, lane = tid & 31, warp = tid >> 5;
  int part = blockIdx.x % 7;
  int bh = blockIdx.x / 7;
  int b = bh >> 3, h = bh & 7;
  const fp16* kHh = KVh + ((size_t)b * 2 * DIM + h * 32) * HWP;
  const fp16* kHl = KVl + ((size_t)b * 2 * DIM + h * 32) * HWP;
  const fp16* vHh = kHh + (size_t)DIM * HWP;
  const fp16* vHl = kHl + (size_t)DIM * HWP;
  const float scal = 0.17677669529663687f;  // 32^-0.5

  for (int t = tid; t < 896; t += 128) {
    int d = t & 31, jg = t >> 5;
    int j0 = jg * 8;
    fp16 th[8], tl[8], uh[8], ul[8];
    if (j0 + 8 <= HWP) {
      const char* pkh = (const char*)(kHh + (size_t)d * HWP + j0);
      const char* pkl = (const char*)(kHl + (size_t)d * HWP + j0);
      const char* pvh = (const char*)(vHh + (size_t)d * HWP + j0);
      const char* pvl = (const char*)(vHl + (size_t)d * HWP + j0);
      *(uint2*)th = *(const uint2*)pkh; *(uint2*)(th + 4) = *(const uint2*)(pkh + 8);
      *(uint2*)tl = *(const uint2*)pkl; *(uint2*)(tl + 4) = *(const uint2*)(pkl + 8);
      *(uint2*)uh = *(const uint2*)pvh; *(uint2*)(uh + 4) = *(const uint2*)(pvh + 8);
      *(uint2*)ul = *(const uint2*)pvl; *(uint2*)(ul + 4) = *(const uint2*)(pvl + 8);
    } else {
      fp16 z = __float2half(0.f);
#pragma unroll
      for (int j = 0; j < 8; j++) {
        int g = j0 + j;
        bool v = g < HWP;
        th[j] = v ? kHh[(size_t)d * HWP + g] : z;
        tl[j] = v ? kHl[(size_t)d * HWP + g] : z;
        uh[j] = v ? vHh[(size_t)d * HWP + g] : z;
        ul[j] = v ? vHl[(size_t)d * HWP + g] : z;
      }
    }
#pragma unroll
    for (int j = 0; j < 8; j++) {
      *(fp16*)(sm + A6_KH + ((j0 + j) * 40 + d) * 2) = th[j];
      *(fp16*)(sm + A6_KL + ((j0 + j) * 40 + d) * 2) = tl[j];
    }
    *(uint4*)(sm + A6_VH + (d * 232 + j0) * 2) = *(uint4*)uh;
    *(uint4*)(sm + A6_VL + (d * 232 + j0) * 2) = *(uint4*)ul;
  }

  const fp16* qbh = Qh + ((size_t)b * DIM + h * 32) * HWX;
  fp16* GFb = GF + ((size_t)b * DIM + h * 32) * HWX;
  int mw = warp * 16;

  for (int it = 0; it < 7; it++) {
    int q0 = (part * 7 + it) * 64;
    __syncthreads();
    for (int t = tid; t < 256; t += 128) {
      int d = t & 31, mg = t >> 5;
      uint4 vh = *(const uint4*)(qbh + (size_t)d * HWX + q0 + mg * 8);
      fp16* eh = (fp16*)&vh;
#pragma unroll
      for (int j = 0; j < 8; j++)
        *(fp16*)(sm + A6_AQH + ((mg * 8 + j) * 40 + d) * 2) = eh[j];
    }
    __syncthreads();

    float acc[26][4];
    uint32_t accH[26][2];
#pragma unroll
    for (int nt = 0; nt < 26; nt++) {
#pragma unroll
      for (int c = 0; c < 4; c++) acc[nt][c] = 0.f;
      accH[nt][0] = 0u; accH[nt][1] = 0u;
    }
    int rn = ((lane >> 4) << 3) + (lane & 7);
    uint32_t kb = ((lane >> 3) & 1) * 16;
#pragma unroll
    for (int s = 0; s < 2; s++) {
      uint32_t ah[4];
      uint32_t aoff = ((mw + (lane & 15)) * 40 + s * 16) * 2 + (lane >> 4) * 16;
      ldm4(ah, sb + A6_AQH + aoff);
#pragma unroll
      for (int np = 0; np < 13; np++) {
        uint32_t boff = (uint32_t)(((np * 16 + rn) * 40 + s * 16) * 2) + kb;
        uint32_t bh4[4], bl4[4];
        ldm4(bh4, sb + A6_KH + boff);
        ldm4(bl4, sb + A6_KL + boff);
        mmaF32(acc[2*np],   ah, bh4);
        mmaF16(accH[2*np],  ah, bl4);
        mmaF32(acc[2*np+1], ah, bh4 + 2);
        mmaF16(accH[2*np+1],ah, bl4 + 2);
      }
    }

    float sum1 = 0.f, sum2 = 0.f;
#pragma unroll
    for (int nt = 0; nt < 26; nt++) {
      int jb = nt * 8 + (lane & 3) * 2;
      float e0 = (acc[nt][0] + hlo(accH[nt][0])) * scal;
      float e1 = (acc[nt][1] + hhi(accH[nt][0])) * scal;
      float e2 = (acc[nt][2] + hlo(accH[nt][1])) * scal;
      float e3 = (acc[nt][3] + hhi(accH[nt][1])) * scal;
      e0 = (jb < HWP)     ? __expf(e0) : 0.f;
      e1 = (jb + 1 < HWP) ? __expf(e1) : 0.f;
      e2 = (jb < HWP)     ? __expf(e2) : 0.f;
      e3 = (jb + 1 < HWP) ? __expf(e3) : 0.f;
      acc[nt][0] = e0; acc[nt][1] = e1; acc[nt][2] = e2; acc[nt][3] = e3;
      sum1 += e0 + e1;
      sum2 += e2 + e3;
    }
#pragma unroll
    for (int o = 1; o <= 2; o <<= 1) {
      sum1 += __shfl_xor_sync(0xffffffffu, sum1, o);
      sum2 += __shfl_xor_sync(0xffffffffu, sum2, o);
    }
    float rec1 = 1.f / sum1, rec2 = 1.f / sum2;

    float acc2[4][4];
    uint32_t acc2H[4][2];
#pragma unroll
    for (int nt = 0; nt < 4; nt++) {
#pragma unroll
      for (int c = 0; c < 4; c++) acc2[nt][c] = 0.f;
      acc2H[nt][0] = 0u; acc2H[nt][1] = 0u;
    }
#pragma unroll 1
    for (int k = 0; k < 13; k++) {
      uint32_t ph[4];
      ph[0] = hpack(acc[2*k][0] * rec1,   acc[2*k][1] * rec1);
      ph[1] = hpack(acc[2*k][2] * rec2,   acc[2*k][3] * rec2);
      ph[2] = hpack(acc[2*k+1][0] * rec1, acc[2*k+1][1] * rec1);
      ph[3] = hpack(acc[2*k+1][2] * rec2, acc[2*k+1][3] * rec2);
#pragma unroll
      for (int np = 0; np < 2; np++) {
        uint32_t boff = (uint32_t)(((np * 16 + rn) * 232 + k * 16) * 2) + kb;
        uint32_t vh4[4], vl4[4];
        ldm4(vh4, sb + A6_VH + boff);
        ldm4(vl4, sb + A6_VL + boff);
        mmaF32(acc2[2*np],   ph, vh4);
        mmaF16(acc2H[2*np],  ph, vl4);
        mmaF32(acc2[2*np+1], ph, vh4 + 2);
        mmaF16(acc2H[2*np+1],ph, vl4 + 2);
      }
    }
    __syncthreads();

    float* Ob = (float*)sm;
    {
      int m1 = mw + (lane >> 2), m2 = m1 + 8;
      int cb = (lane & 3) * 2;
#pragma unroll
      for (int nt = 0; nt < 4; nt++) {
        int dcol = nt * 8 + cb;
        Ob[dcol * 68 + m1]       = acc2[nt][0] + hlo(acc2H[nt][0]);
        Ob[(dcol + 1) * 68 + m1] = acc2[nt][1] + hhi(acc2H[nt][0]);
        Ob[dcol * 68 + m2]       = acc2[nt][2] + hlo(acc2H[nt][1]);
        Ob[(dcol + 1) * 68 + m2] = acc2[nt][3] + hhi(acc2H[nt][1]);
      }
    }
    __syncthreads();
    {
      int row = tid >> 2, i0 = (tid & 3) * 16;
#pragma unroll
      for (int c = 0; c < 4; c++) {
        int i = i0 + c * 4;
        float4 v = *(float4*)&Ob[row * 68 + i];
        __half2 p0 = __floats2half2_rn(v.x, v.y);
        __half2 p1 = __floats2half2_rn(v.z, v.w);
        uint2 pk = make_uint2(*(uint32_t*)&p0, *(uint32_t*)&p1);
        *(uint2*)&GFb[(size_t)row * HWX + q0 + i] = pk;
      }
    }
  }
}

extern "C" void kernel_launch(void* const* d_in, const int* in_sizes, int n_in,
                              void* d_out, int out_size) {
  const float* x     = (const float*)d_in[0];
  const float* q_w   = (const float*)d_in[1];
  const float* q_b   = (const float*)d_in[2];
  const float* kv_w  = (const float*)d_in[3];
  const float* kv_b  = (const float*)d_in[4];
  const float* p0_w  = (const float*)d_in[5];
  const float* p0_b  = (const float*)d_in[6];
  const float* bn0_g = (const float*)d_in[7];
  const float* bn0_b = (const float*)d_in[8];
  const float* bn0_m = (const float*)d_in[9];
  const float* bn0_v = (const float*)d_in[10];
  const float* pl0_w = (const float*)d_in[11];
  const float* pl0_b = (const float*)d_in[12];
  const float* p1_w  = (const float*)d_in[13];
  const float* p1_b  = (const float*)d_in[14];
  const float* bn1_g = (const float*)d_in[15];
  const float* bn1_b = (const float*)d_in[16];
  const float* bn1_m = (const float*)d_in[17];
  const float* bn1_v = (const float*)d_in[18];
  const float* loc_w = (const float*)d_in[19];
  const float* loc_b = (const float*)d_in[20];
  const float* mix_w = (const float*)d_in[21];
  const float* mix_b = (const float*)d_in[22];
  float* out = (float*)d_out;

  fp16 *xh, *qh, *mh, *gf16, *p0h, *pm16, *pfh, *kvh, *kvl, *wh, *wl;
  cudaGetSymbolAddress((void**)&xh, g_xh);
  cudaGetSymbolAddress((void**)&qh, g_qh);
  cudaGetSymbolAddress((void**)&mh, g_mh);
  cudaGetSymbolAddress((void**)&gf16, g_gf16);
  cudaGetSymbolAddress((void**)&p0h, g_p0h);
  cudaGetSymbolAddress((void**)&pm16, g_pm16);
  cudaGetSymbolAddress((void**)&pfh, g_pfh);
  cudaGetSymbolAddress((void**)&kvh, g_kvh); cudaGetSymbolAddress((void**)&kvl, g_kvl);
  cudaGetSymbolAddress((void**)&wh, g_wh);   cudaGetSymbolAddress((void**)&wl, g_wl);

  cudaFuncSetAttribute(conv1x1_hf_kernel, cudaFuncAttributeMaxDynamicSharedMemorySize, CV_SMEM);
  cudaFuncSetAttribute(attn7_kernel, cudaFuncAttributeMaxDynamicSharedMemorySize, A6_BYTES);

  // 0. pre-split: all weights in one launch; x hi
  cvt_h_kernel<<<(NX/4 + 255)/256, 256>>>(x, xh, NX/4);
  cvt_w_kernel<<<(NW/4 + 255)/256, 256>>>(q_w, pl0_w, kv_w, mix_w, wh, wl);

  // 1. q_local -> fp16 hi (attention Q + gate input)
  conv1x1_hf_kernel<<<dim3((HWX + 127)/128, DIM/128, BATCH), 256, CV_SMEM>>>(
      wh + WOFF_Q, wl + WOFF_Q, xh, q_b, (float*)nullptr, qh, (fp16*)nullptr, DIM, DIM, HWX);
  // 2. p0 = BN0(dw5x5_s2(xh)) -> fp16  (vertical 4-wide, fp16 input)
  dw1h_y4_kernel<<<(BATCH*DIM*7*HP1 + 255)/256, 256>>>(
      xh, p0_w, p0_b, bn0_g, bn0_b, bn0_m, bn0_v, p0h);
  // 3. pmid = conv1x1(p0) -> fp16
  conv1x1_hf_kernel<<<dim3((HW1 + 127)/128, DIM/128, BATCH), 256, CV_SMEM>>>(
      wh + WOFF_PL, wl + WOFF_PL, p0h, pl0_b, (float*)nullptr, pm16, (fp16*)nullptr, DIM, DIM, HW1);
  // 4. pfin = BN1(dw5x5_s2(pmid)) -> fp16 (vertical 4-wide)
  dw2_y4_kernel<<<(BATCH*DIM*4*HP2 + 255)/256, 256>>>(
      pm16, p1_w, p1_b, bn1_g, bn1_b, bn1_m, bn1_v, pfh);
  // 5. kv = conv1x1(pfin) -> fp16 hi/lo
  conv1x1_hf_kernel<<<dim3((HWP + 127)/128, (2*DIM)/128, BATCH), 256, CV_SMEM>>>(
      wh + WOFF_KV, wl + WOFF_KV, pfh, kv_b, (float*)nullptr, kvh, kvl, 2*DIM, DIM, HWP);
  // 6. attention -> gf16
  attn7_kernel<<<BATCH*HEADS*7, 128, A6_BYTES>>>(qh, kvh, kvl, gf16);
  // 7. local mixer + gating (vertical 4-wide) -> mh
  gate_y4_kernel<<<(BATCH*DIM*14*WW + 255)/256, 256>>>(qh, loc_w, loc_b, gf16, mh);
  // 8. out = conv1x1(mixbuf) -> f32
  conv1x1_hf_kernel<<<dim3((HWX + 127)/128, DIM/128, BATCH), 256, CV_SMEM>>>(
      wh + WOFF_MIX, wl + WOFF_MIX, mh, mix_b, out, (fp16*)nullptr, (fp16*)nullptr, DIM, DIM, HWX);
}

// round 17
// speedup vs baseline: 1.7691x; 1.0345x over previous
#include <cuda_runtime.h>
#include <cuda_fp16.h>
#include <cstdint>

#define BATCH 16
#define DIM 256
#define HH 56
#define WW 56
#define HWX (HH*WW)          // 3136
#define HEADS 8
#define DH 32
#define HP1 28
#define HW1 (HP1*HP1)        // 784
#define HP2 14
#define HWP (HP2*HP2)        // 196
#define BN_EPS 1e-5f

#define SW128(x) ((x) ^ (((x) >> 3) & 0x70))

typedef __half fp16;

__device__ __forceinline__ uint32_t smem_u32(const void* p) {
  uint32_t a;
  asm("{ .reg .u64 t; cvta.to.shared.u64 t, %1; cvt.u32.u64 %0, t; }" : "=r"(a) : "l"(p));
  return a;
}
__device__ __forceinline__ void ldm4(uint32_t a[4], uint32_t addr) {
  asm volatile("ldmatrix.sync.aligned.m8n8.x4.shared.b16 {%0,%1,%2,%3}, [%4];"
               : "=r"(a[0]), "=r"(a[1]), "=r"(a[2]), "=r"(a[3]) : "r"(addr));
}
__device__ __forceinline__ void ldm4t(uint32_t a[4], uint32_t addr) {
  asm volatile("ldmatrix.sync.aligned.m8n8.x4.trans.shared.b16 {%0,%1,%2,%3}, [%4];"
               : "=r"(a[0]), "=r"(a[1]), "=r"(a[2]), "=r"(a[3]) : "r"(addr));
}
__device__ __forceinline__ void mmaF32(float d[4], const uint32_t a[4], const uint32_t b[2]) {
  asm volatile("mma.sync.aligned.m16n8k16.row.col.f32.f16.f16.f32 "
               "{%0,%1,%2,%3}, {%4,%5,%6,%7}, {%8,%9}, {%0,%1,%2,%3};"
               : "+f"(d[0]), "+f"(d[1]), "+f"(d[2]), "+f"(d[3])
               : "r"(a[0]), "r"(a[1]), "r"(a[2]), "r"(a[3]), "r"(b[0]), "r"(b[1]));
}
__device__ __forceinline__ void mmaF16(uint32_t d[2], const uint32_t a[4], const uint32_t b[2]) {
  asm volatile("mma.sync.aligned.m16n8k16.row.col.f16.f16.f16.f16 "
               "{%0,%1}, {%2,%3,%4,%5}, {%6,%7}, {%0,%1};"
               : "+r"(d[0]), "+r"(d[1])
               : "r"(a[0]), "r"(a[1]), "r"(a[2]), "r"(a[3]), "r"(b[0]), "r"(b[1]));
}
__device__ __forceinline__ uint32_t hpack(float a, float b) {
  __half2 t = __floats2half2_rn(a, b);
  return *(uint32_t*)&t;
}
__device__ __forceinline__ float hlo(uint32_t v) { return __half2float(((__half2*)&v)->x); }
__device__ __forceinline__ float hhi(uint32_t v) { return __half2float(((__half2*)&v)->y); }

// ---------------- scratch (device globals; no allocations allowed) ----------------
#define NX (BATCH*DIM*HWX)
#define NP0 (BATCH*DIM*HW1)
#define NPF (BATCH*DIM*HWP)
#define NKV (BATCH*2*DIM*HWP)
#define WOFF_Q 0
#define WOFF_PL 65536
#define WOFF_KV 131072
#define WOFF_MIX 262144
#define NW 327680
__device__ fp16 g_xh[NX];
__device__ fp16 g_qh[NX];
__device__ fp16 g_mh[NX];
__device__ fp16 g_gf16[NX];
__device__ fp16 g_p0h[NP0];
__device__ fp16 g_pm16[NP0];
__device__ fp16 g_pfh[NPF];
__device__ fp16 g_kvh[NKV], g_kvl[NKV];
__device__ fp16 g_wh[NW],  g_wl[NW];

// ---------------- x -> fp16 hi ----------------
__global__ __launch_bounds__(256) void cvt_h_kernel(
    const float* __restrict__ s, fp16* __restrict__ h, int n4) {
  int i = blockIdx.x * 256 + threadIdx.x;
  if (i >= n4) return;
  float4 v = ((const float4*)s)[i];
  ((__half2*)h)[2*i]   = __floats2half2_rn(v.x, v.y);
  ((__half2*)h)[2*i+1] = __floats2half2_rn(v.z, v.w);
}
// ---------------- fused weight hi/lo split ----------------
__global__ __launch_bounds__(256) void cvt_w_kernel(
    const float* __restrict__ qw, const float* __restrict__ plw,
    const float* __restrict__ kvw, const float* __restrict__ mxw,
    fp16* __restrict__ h, fp16* __restrict__ l) {
  int i = blockIdx.x * 256 + threadIdx.x;
  if (i >= NW / 4) return;
  const float* src;
  int li;
  if (i < 16384)      { src = qw;  li = i; }
  else if (i < 32768) { src = plw; li = i - 16384; }
  else if (i < 65536) { src = kvw; li = i - 32768; }
  else                { src = mxw; li = i - 65536; }
  float4 v = ((const float4*)src)[li];
  __half2 h0 = __floats2half2_rn(v.x, v.y);
  __half2 h1 = __floats2half2_rn(v.z, v.w);
  __half2 l0 = __floats2half2_rn(v.x - __half2float(h0.x), v.y - __half2float(h0.y));
  __half2 l1 = __floats2half2_rn(v.z - __half2float(h1.x), v.w - __half2float(h1.y));
  ((__half2*)h)[2*i] = h0; ((__half2*)h)[2*i+1] = h1;
  ((__half2*)l)[2*i] = l0; ((__half2*)l)[2*i+1] = l1;
}

// ---------------- 1x1 conv: 2-pass split-fp16 HMMA, x4-trans B loads ----------------
#define CV_SMEM 49152

__global__ __launch_bounds__(256) void conv1x1_hf_kernel(
    const fp16* __restrict__ Ah, const fp16* __restrict__ Al,
    const fp16* __restrict__ Bh,
    const float* __restrict__ bias, float* __restrict__ Yf,
    fp16* __restrict__ Yh, fp16* __restrict__ Yl,
    int CO, int CI, int HW) {
  extern __shared__ __align__(1024) char smem[];
  char* sAh = smem;         char* sAl = smem + 16384;
  char* sBh = smem + 32768;
  uint32_t aAh = smem_u32(sAh), aAl = smem_u32(sAl);
  uint32_t aBh = smem_u32(sBh);
  int tid = threadIdx.x, lane = tid & 31, wid = tid >> 5;
  int m0 = blockIdx.y * 128, n0 = blockIdx.x * 128;
  const fp16* Bhb = Bh + (size_t)blockIdx.z * CI * HW;
  int mw = (wid & 3) * 32, nw = (wid >> 2) * 64;

  float acc[2][8][4];
  uint32_t accH[2][8][2];
#pragma unroll
  for (int i = 0; i < 2; i++)
#pragma unroll
    for (int j = 0; j < 8; j++) {
#pragma unroll
      for (int c = 0; c < 4; c++) acc[i][j][c] = 0.f;
      accH[i][j][0] = 0u; accH[i][j][1] = 0u;
    }

  for (int k0 = 0; k0 < CI; k0 += 64) {
#pragma unroll
    for (int i = 0; i < 4; i++) {
      int t = tid + i * 256;
      int m = t >> 3, kg = t & 7;
      size_t src = (size_t)(m0 + m) * CI + k0 + kg * 8;
      uint32_t dst = SW128(m * 128 + kg * 16);
      *(uint4*)(sAh + dst) = *(const uint4*)(Ah + src);
      *(uint4*)(sAl + dst) = *(const uint4*)(Al + src);
    }
#pragma unroll
    for (int i = 0; i < 4; i++) {
      int t = tid + i * 256;
      int k = t & 63, c = t >> 6;
      int gn = n0 + c * 8;
      uint4 vh;
      if (gn + 8 <= HW) {
        const char* ph = (const char*)(Bhb + (size_t)(k0 + k) * HW + gn);
        uint2 h0 = *(const uint2*)ph, h1 = *(const uint2*)(ph + 8);
        vh = make_uint4(h0.x, h0.y, h1.x, h1.y);
      } else {
        fp16 th[8];
#pragma unroll
        for (int j = 0; j < 8; j++) {
          int g = gn + j;
          th[j] = (g < HW) ? Bhb[(size_t)(k0 + k) * HW + g] : __float2half(0.f);
        }
        vh = *(uint4*)th;
      }
      *(uint4*)(sBh + (k * 256 + ((c ^ (k & 15)) << 4))) = vh;
    }
    __syncthreads();
#pragma unroll
    for (int s = 0; s < 4; s++) {
      uint32_t ah[2][4], al[2][4];
#pragma unroll
      for (int tm = 0; tm < 2; tm++) {
        uint32_t off = SW128((mw + tm * 16 + (lane & 15)) * 128 + s * 32 + (lane >> 4) * 16);
        ldm4(ah[tm], aAh + off);
        ldm4(al[tm], aAl + off);
      }
      int kk = s * 16 + (lane & 15);
#pragma unroll
      for (int ntp = 0; ntp < 4; ntp++) {
        int nt_eff = 2 * ntp + (lane >> 4);
        uint32_t cIdx = (uint32_t)(((nw >> 3) + nt_eff) ^ (kk & 15));
        uint32_t bq[4];
        ldm4t(bq, aBh + kk * 256 + (cIdx << 4));
#pragma unroll
        for (int tm = 0; tm < 2; tm++) {
          mmaF32(acc[tm][2*ntp],   ah[tm], bq);
          mmaF16(accH[tm][2*ntp],  al[tm], bq);
          mmaF32(acc[tm][2*ntp+1], ah[tm], bq + 2);
          mmaF16(accH[tm][2*ntp+1],al[tm], bq + 2);
        }
      }
    }
    __syncthreads();
  }
#pragma unroll
  for (int tm = 0; tm < 2; tm++) {
    int r0 = m0 + mw + tm * 16 + (lane >> 2);
    float b0 = bias[r0], b1 = bias[r0 + 8];
#pragma unroll
    for (int tn = 0; tn < 8; tn++) {
      int col = n0 + nw + tn * 8 + (lane & 3) * 2;
      if (col < HW) {
        float o0 = acc[tm][tn][0] + hlo(accH[tm][tn][0]) + b0;
        float o1 = acc[tm][tn][1] + hhi(accH[tm][tn][0]) + b0;
        float o2 = acc[tm][tn][2] + hlo(accH[tm][tn][1]) + b1;
        float o3 = acc[tm][tn][3] + hhi(accH[tm][tn][1]) + b1;
        size_t i0 = (size_t)blockIdx.z * CO * HW + (size_t)r0 * HW + col;
        size_t i1 = i0 + (size_t)8 * HW;
        if (Yf) {
          *(float2*)&Yf[i0] = make_float2(o0, o1);
          *(float2*)&Yf[i1] = make_float2(o2, o3);
        }
        if (Yh) {
          __half2 h0 = __floats2half2_rn(o0, o1);
          __half2 h1 = __floats2half2_rn(o2, o3);
          *(__half2*)&Yh[i0] = h0; *(__half2*)&Yh[i1] = h1;
          if (Yl) {
            __half2 l0 = __floats2half2_rn(o0 - __half2float(h0.x), o1 - __half2float(h0.y));
            __half2 l1 = __floats2half2_rn(o2 - __half2float(h1.x), o3 - __half2float(h1.y));
            *(__half2*)&Yl[i0] = l0; *(__half2*)&Yl[i1] = l1;
          }
        }
      }
    }
  }
}

// ---------------- dw1: 5x5 s2 + BN, fp16 in -> fp16, 4 outputs along y ----------------
__global__ __launch_bounds__(256) void dw1h_y4_kernel(
    const fp16* __restrict__ X, const float* __restrict__ Wd,
    const float* __restrict__ bias, const float* __restrict__ gam,
    const float* __restrict__ bet, const float* __restrict__ mu,
    const float* __restrict__ var, fp16* __restrict__ Yh) {
  int idx = blockIdx.x * 256 + threadIdx.x;
  int total = BATCH * DIM * 7 * HP1;
  if (idx >= total) return;
  int x = idx % HP1; int t = idx / HP1;
  int yg = t % 7; t /= 7;
  int c = t % DIM; int b = t / DIM;
  int oy0 = yg * 4;
  const fp16* xp = X + (size_t)(b * DIM + c) * HWX;
  const float* wp = Wd + c * 25;
  float sums[4] = {0.f, 0.f, 0.f, 0.f};
#pragma unroll
  for (int rr = 0; rr < 11; rr++) {
    int iy = oy0 * 2 - 2 + rr;
    if (iy < 0 || iy >= HH) continue;
    const fp16* row = xp + iy * WW;
    float rv[5];
#pragma unroll
    for (int kx = 0; kx < 5; kx++) {
      int ix = x * 2 - 2 + kx;
      rv[kx] = (ix >= 0 && ix < WW) ? __half2float(row[ix]) : 0.f;
    }
#pragma unroll
    for (int o = 0; o < 4; o++) {
      int ky = rr - 2 * o;
      if (ky >= 0 && ky < 5) {
#pragma unroll
        for (int kx = 0; kx < 5; kx++) sums[o] += rv[kx] * wp[ky * 5 + kx];
      }
    }
  }
  float bsv = bias[c];
  float sc = gam[c] * rsqrtf(var[c] + BN_EPS);
  float muv = mu[c], bev = bet[c];
  size_t ob = ((size_t)(b * DIM + c) * HP1 + oy0) * HP1 + x;
#pragma unroll
  for (int o = 0; o < 4; o++)
    Yh[ob + (size_t)o * HP1] = __float2half_rn((sums[o] + bsv - muv) * sc + bev);
}

// ---------------- dw2: 5x5 s2 + BN, fp16 in -> fp16, 4 outputs along y (bounds) -------
__global__ __launch_bounds__(256) void dw2_y4_kernel(
    const fp16* __restrict__ X, const float* __restrict__ Wd,
    const float* __restrict__ bias, const float* __restrict__ gam,
    const float* __restrict__ bet, const float* __restrict__ mu,
    const float* __restrict__ var, fp16* __restrict__ Yh) {
  int idx = blockIdx.x * 256 + threadIdx.x;
  int total = BATCH * DIM * 4 * HP2;
  if (idx >= total) return;
  int x = idx % HP2; int t = idx / HP2;
  int yg = t % 4; t /= 4;
  int c = t % DIM; int b = t / DIM;
  int oy0 = yg * 4;
  const fp16* xp = X + (size_t)(b * DIM + c) * HW1;
  const float* wp = Wd + c * 25;
  float sums[4] = {0.f, 0.f, 0.f, 0.f};
#pragma unroll
  for (int rr = 0; rr < 11; rr++) {
    int iy = oy0 * 2 - 2 + rr;
    if (iy < 0 || iy >= HP1) continue;
    const fp16* row = xp + iy * HP1;
    float rv[5];
#pragma unroll
    for (int kx = 0; kx < 5; kx++) {
      int ix = x * 2 - 2 + kx;
      rv[kx] = (ix >= 0 && ix < HP1) ? __half2float(row[ix]) : 0.f;
    }
#pragma unroll
    for (int o = 0; o < 4; o++) {
      int ky = rr - 2 * o;
      if (ky >= 0 && ky < 5) {
#pragma unroll
        for (int kx = 0; kx < 5; kx++) sums[o] += rv[kx] * wp[ky * 5 + kx];
      }
    }
  }
  float bsv = bias[c];
  float sc = gam[c] * rsqrtf(var[c] + BN_EPS);
  float muv = mu[c], bev = bet[c];
  size_t ob = ((size_t)(b * DIM + c) * HP2 + oy0) * HP2 + x;
#pragma unroll
  for (int o = 0; o < 4; o++)
    if (oy0 + o < HP2)
      Yh[ob + (size_t)o * HP2] = __float2half_rn((sums[o] + bsv - muv) * sc + bev);
}

// ---------------- gate: dw5x5 s1 + SiLU + sigmoid-gate, 4 outputs along y -------------
__global__ __launch_bounds__(256) void gate_y4_kernel(
    const fp16* __restrict__ Q, const float* __restrict__ Wd,
    const float* __restrict__ bias, const fp16* __restrict__ G,
    fp16* __restrict__ Oh) {
  int idx = blockIdx.x * 256 + threadIdx.x;
  int total = BATCH * DIM * 14 * WW;
  if (idx >= total) return;
  int x = idx % WW; int t = idx / WW;
  int yg = t % 14; t /= 14;
  int c = t % DIM; int b = t / DIM;
  int oy0 = yg * 4;
  const fp16* xp = Q + (size_t)(b * DIM + c) * HWX;
  const float* wp = Wd + c * 25;
  float sums[4] = {0.f, 0.f, 0.f, 0.f};
#pragma unroll
  for (int rr = 0; rr < 8; rr++) {
    int iy = oy0 - 2 + rr;
    if (iy < 0 || iy >= HH) continue;
    const fp16* row = xp + iy * WW;
    float rv[5];
#pragma unroll
    for (int kx = 0; kx < 5; kx++) {
      int ix = x - 2 + kx;
      rv[kx] = (ix >= 0 && ix < WW) ? __half2float(row[ix]) : 0.f;
    }
#pragma unroll
    for (int o = 0; o < 4; o++) {
      int ky = rr - o;
      if (ky >= 0 && ky < 5) {
#pragma unroll
        for (int kx = 0; kx < 5; kx++) sums[o] += rv[kx] * wp[ky * 5 + kx];
      }
    }
  }
  float bsv = bias[c];
  size_t ob = (size_t)(b * DIM + c) * HWX + (size_t)oy0 * WW + x;
#pragma unroll
  for (int o = 0; o < 4; o++) {
    float s = sums[o] + bsv;
    float lf = s / (1.f + __expf(-s));
    float gv = __half2float(G[ob + (size_t)o * WW]);
    float sg = 1.f / (1.f + __expf(-gv));
    Oh[ob + (size_t)o * WW] = __float2half_rn(lf * sg * gv);
  }
}

// ---------------- attention v7: x4 B-loads, no max-pass, fp16 output, 3 CTA/SM --------
#define A6_AQH 0
#define A6_KH  8704
#define A6_KL  26624
#define A6_VH  44544
#define A6_VL  59392
#define A6_BYTES 74240

__global__ __launch_bounds__(128, 3) void attn7_kernel(
    const fp16* __restrict__ Qh,
    const fp16* __restrict__ KVh, const fp16* __restrict__ KVl,
    fp16* __restrict__ GF) {
  extern __shared__ __align__(1024) char sm[];
  uint32_t sb = smem_u32(sm);
  int tid = threadIdx.x, lane = tid & 31, warp = tid >> 5;
  int part = blockIdx.x % 7;
  int bh = blockIdx.x / 7;
  int b = bh >> 3, h = bh & 7;
  const fp16* kHh = KVh + ((size_t)b * 2 * DIM + h * 32) * HWP;
  const fp16* kHl = KVl + ((size_t)b * 2 * DIM + h * 32) * HWP;
  const fp16* vHh = kHh + (size_t)DIM * HWP;
  const fp16* vHl = kHl + (size_t)DIM * HWP;
  const float scal = 0.17677669529663687f;  // 32^-0.5

  for (int t = tid; t < 896; t += 128) {
    int d = t & 31, jg = t >> 5;
    int j0 = jg * 8;
    fp16 th[8], tl[8], uh[8], ul[8];
    if (j0 + 8 <= HWP) {
      const char* pkh = (const char*)(kHh + (size_t)d * HWP + j0);
      const char* pkl = (const char*)(kHl + (size_t)d * HWP + j0);
      const char* pvh = (const char*)(vHh + (size_t)d * HWP + j0);
      const char* pvl = (const char*)(vHl + (size_t)d * HWP + j0);
      *(uint2*)th = *(const uint2*)pkh; *(uint2*)(th + 4) = *(const uint2*)(pkh + 8);
      *(uint2*)tl = *(const uint2*)pkl; *(uint2*)(tl + 4) = *(const uint2*)(pkl + 8);
      *(uint2*)uh = *(const uint2*)pvh; *(uint2*)(uh + 4) = *(const uint2*)(pvh + 8);
      *(uint2*)ul = *(const uint2*)pvl; *(uint2*)(ul + 4) = *(const uint2*)(pvl + 8);
    } else {
      fp16 z = __float2half(0.f);
#pragma unroll
      for (int j = 0; j < 8; j++) {
        int g = j0 + j;
        bool v = g < HWP;
        th[j] = v ? kHh[(size_t)d * HWP + g] : z;
        tl[j] = v ? kHl[(size_t)d * HWP + g] : z;
        uh[j] = v ? vHh[(size_t)d * HWP + g] : z;
        ul[j] = v ? vHl[(size_t)d * HWP + g] : z;
      }
    }
#pragma unroll
    for (int j = 0; j < 8; j++) {
      *(fp16*)(sm + A6_KH + ((j0 + j) * 40 + d) * 2) = th[j];
      *(fp16*)(sm + A6_KL + ((j0 + j) * 40 + d) * 2) = tl[j];
    }
    *(uint4*)(sm + A6_VH + (d * 232 + j0) * 2) = *(uint4*)uh;
    *(uint4*)(sm + A6_VL + (d * 232 + j0) * 2) = *(uint4*)ul;
  }

  const fp16* qbh = Qh + ((size_t)b * DIM + h * 32) * HWX;
  fp16* GFb = GF + ((size_t)b * DIM + h * 32) * HWX;
  int mw = warp * 16;

  for (int it = 0; it < 7; it++) {
    int q0 = (part * 7 + it) * 64;
    __syncthreads();
    for (int t = tid; t < 256; t += 128) {
      int d = t & 31, mg = t >> 5;
      uint4 vh = *(const uint4*)(qbh + (size_t)d * HWX + q0 + mg * 8);
      fp16* eh = (fp16*)&vh;
#pragma unroll
      for (int j = 0; j < 8; j++)
        *(fp16*)(sm + A6_AQH + ((mg * 8 + j) * 40 + d) * 2) = eh[j];
    }
    __syncthreads();

    float acc[26][4];
    uint32_t accH[26][2];
#pragma unroll
    for (int nt = 0; nt < 26; nt++) {
#pragma unroll
      for (int c = 0; c < 4; c++) acc[nt][c] = 0.f;
      accH[nt][0] = 0u; accH[nt][1] = 0u;
    }
    int rn = ((lane >> 4) << 3) + (lane & 7);
    uint32_t kb = ((lane >> 3) & 1) * 16;
#pragma unroll
    for (int s = 0; s < 2; s++) {
      uint32_t ah[4];
      uint32_t aoff = ((mw + (lane & 15)) * 40 + s * 16) * 2 + (lane >> 4) * 16;
      ldm4(ah, sb + A6_AQH + aoff);
#pragma unroll
      for (int np = 0; np < 13; np++) {
        uint32_t boff = (uint32_t)(((np * 16 + rn) * 40 + s * 16) * 2) + kb;
        uint32_t bh4[4], bl4[4];
        ldm4(bh4, sb + A6_KH + boff);
        ldm4(bl4, sb + A6_KL + boff);
        mmaF32(acc[2*np],   ah, bh4);
        mmaF16(accH[2*np],  ah, bl4);
        mmaF32(acc[2*np+1], ah, bh4 + 2);
        mmaF16(accH[2*np+1],ah, bl4 + 2);
      }
    }

    float sum1 = 0.f, sum2 = 0.f;
#pragma unroll
    for (int nt = 0; nt < 26; nt++) {
      int jb = nt * 8 + (lane & 3) * 2;
      float e0 = (acc[nt][0] + hlo(accH[nt][0])) * scal;
      float e1 = (acc[nt][1] + hhi(accH[nt][0])) * scal;
      float e2 = (acc[nt][2] + hlo(accH[nt][1])) * scal;
      float e3 = (acc[nt][3] + hhi(accH[nt][1])) * scal;
      e0 = (jb < HWP)     ? __expf(e0) : 0.f;
      e1 = (jb + 1 < HWP) ? __expf(e1) : 0.f;
      e2 = (jb < HWP)     ? __expf(e2) : 0.f;
      e3 = (jb + 1 < HWP) ? __expf(e3) : 0.f;
      acc[nt][0] = e0; acc[nt][1] = e1; acc[nt][2] = e2; acc[nt][3] = e3;
      sum1 += e0 + e1;
      sum2 += e2 + e3;
    }
#pragma unroll
    for (int o = 1; o <= 2; o <<= 1) {
      sum1 += __shfl_xor_sync(0xffffffffu, sum1, o);
      sum2 += __shfl_xor_sync(0xffffffffu, sum2, o);
    }
    float rec1 = 1.f / sum1, rec2 = 1.f / sum2;

    float acc2[4][4];
    uint32_t acc2H[4][2];
#pragma unroll
    for (int nt = 0; nt < 4; nt++) {
#pragma unroll
      for (int c = 0; c < 4; c++) acc2[nt][c] = 0.f;
      acc2H[nt][0] = 0u; acc2H[nt][1] = 0u;
    }
#pragma unroll 1
    for (int k = 0; k < 13; k++) {
      uint32_t ph[4];
      ph[0] = hpack(acc[2*k][0] * rec1,   acc[2*k][1] * rec1);
      ph[1] = hpack(acc[2*k][2] * rec2,   acc[2*k][3] * rec2);
      ph[2] = hpack(acc[2*k+1][0] * rec1, acc[2*k+1][1] * rec1);
      ph[3] = hpack(acc[2*k+1][2] * rec2, acc[2*k+1][3] * rec2);
#pragma unroll
      for (int np = 0; np < 2; np++) {
        uint32_t boff = (uint32_t)(((np * 16 + rn) * 232 + k * 16) * 2) + kb;
        uint32_t vh4[4], vl4[4];
        ldm4(vh4, sb + A6_VH + boff);
        ldm4(vl4, sb + A6_VL + boff);
        mmaF32(acc2[2*np],   ph, vh4);
        mmaF16(acc2H[2*np],  ph, vl4);
        mmaF32(acc2[2*np+1], ph, vh4 + 2);
        mmaF16(acc2H[2*np+1],ph, vl4 + 2);
      }
    }
    __syncthreads();

    float* Ob = (float*)sm;
    {
      int m1 = mw + (lane >> 2), m2 = m1 + 8;
      int cb = (lane & 3) * 2;
#pragma unroll
      for (int nt = 0; nt < 4; nt++) {
        int dcol = nt * 8 + cb;
        Ob[dcol * 68 + m1]       = acc2[nt][0] + hlo(acc2H[nt][0]);
        Ob[(dcol + 1) * 68 + m1] = acc2[nt][1] + hhi(acc2H[nt][0]);
        Ob[dcol * 68 + m2]       = acc2[nt][2] + hlo(acc2H[nt][1]);
        Ob[(dcol + 1) * 68 + m2] = acc2[nt][3] + hhi(acc2H[nt][1]);
      }
    }
    __syncthreads();
    {
      int row = tid >> 2, i0 = (tid & 3) * 16;
#pragma unroll
      for (int c = 0; c < 4; c++) {
        int i = i0 + c * 4;
        float4 v = *(float4*)&Ob[row * 68 + i];
        __half2 p0 = __floats2half2_rn(v.x, v.y);
        __half2 p1 = __floats2half2_rn(v.z, v.w);
        uint2 pk = make_uint2(*(uint32_t*)&p0, *(uint32_t*)&p1);
        *(uint2*)&GFb[(size_t)row * HWX + q0 + i] = pk;
      }
    }
  }
}

extern "C" void kernel_launch(void* const* d_in, const int* in_sizes, int n_in,
                              void* d_out, int out_size) {
  const float* x     = (const float*)d_in[0];
  const float* q_w   = (const float*)d_in[1];
  const float* q_b   = (const float*)d_in[2];
  const float* kv_w  = (const float*)d_in[3];
  const float* kv_b  = (const float*)d_in[4];
  const float* p0_w  = (const float*)d_in[5];
  const float* p0_b  = (const float*)d_in[6];
  const float* bn0_g = (const float*)d_in[7];
  const float* bn0_b = (const float*)d_in[8];
  const float* bn0_m = (const float*)d_in[9];
  const float* bn0_v = (const float*)d_in[10];
  const float* pl0_w = (const float*)d_in[11];
  const float* pl0_b = (const float*)d_in[12];
  const float* p1_w  = (const float*)d_in[13];
  const float* p1_b  = (const float*)d_in[14];
  const float* bn1_g = (const float*)d_in[15];
  const float* bn1_b = (const float*)d_in[16];
  const float* bn1_m = (const float*)d_in[17];
  const float* bn1_v = (const float*)d_in[18];
  const float* loc_w = (const float*)d_in[19];
  const float* loc_b = (const float*)d_in[20];
  const float* mix_w = (const float*)d_in[21];
  const float* mix_b = (const float*)d_in[22];
  float* out = (float*)d_out;

  fp16 *xh, *qh, *mh, *gf16, *p0h, *pm16, *pfh, *kvh, *kvl, *wh, *wl;
  cudaGetSymbolAddress((void**)&xh, g_xh);
  cudaGetSymbolAddress((void**)&qh, g_qh);
  cudaGetSymbolAddress((void**)&mh, g_mh);
  cudaGetSymbolAddress((void**)&gf16, g_gf16);
  cudaGetSymbolAddress((void**)&p0h, g_p0h);
  cudaGetSymbolAddress((void**)&pm16, g_pm16);
  cudaGetSymbolAddress((void**)&pfh, g_pfh);
  cudaGetSymbolAddress((void**)&kvh, g_kvh); cudaGetSymbolAddress((void**)&kvl, g_kvl);
  cudaGetSymbolAddress((void**)&wh, g_wh);   cudaGetSymbolAddress((void**)&wl, g_wl);

  cudaFuncSetAttribute(conv1x1_hf_kernel, cudaFuncAttributeMaxDynamicSharedMemorySize, CV_SMEM);
  cudaFuncSetAttribute(attn7_kernel, cudaFuncAttributeMaxDynamicSharedMemorySize, A6_BYTES);

  // fork/join side stream (host objects; created per call, not cached;
  // intentionally not destroyed here — capture is still active on return)
  cudaStream_t s2;
  cudaEvent_t eFork, eJoin;
  cudaStreamCreateWithFlags(&s2, cudaStreamNonBlocking);
  cudaEventCreateWithFlags(&eFork, cudaEventDisableTiming);
  cudaEventCreateWithFlags(&eJoin, cudaEventDisableTiming);

  // 0. pre-split on main stream
  cvt_h_kernel<<<(NX/4 + 255)/256, 256>>>(x, xh, NX/4);
  cvt_w_kernel<<<(NW/4 + 255)/256, 256>>>(q_w, pl0_w, kv_w, mix_w, wh, wl);

  // fork: KV chain on s2, Q conv on main
  cudaEventRecord(eFork, 0);
  cudaStreamWaitEvent(s2, eFork, 0);

  // -- s2: dw1 -> pl0 conv -> dw2 -> kv conv
  dw1h_y4_kernel<<<(BATCH*DIM*7*HP1 + 255)/256, 256, 0, s2>>>(
      xh, p0_w, p0_b, bn0_g, bn0_b, bn0_m, bn0_v, p0h);
  conv1x1_hf_kernel<<<dim3((HW1 + 127)/128, DIM/128, BATCH), 256, CV_SMEM, s2>>>(
      wh + WOFF_PL, wl + WOFF_PL, p0h, pl0_b, (float*)nullptr, pm16, (fp16*)nullptr, DIM, DIM, HW1);
  dw2_y4_kernel<<<(BATCH*DIM*4*HP2 + 255)/256, 256, 0, s2>>>(
      pm16, p1_w, p1_b, bn1_g, bn1_b, bn1_m, bn1_v, pfh);
  conv1x1_hf_kernel<<<dim3((HWP + 127)/128, (2*DIM)/128, BATCH), 256, CV_SMEM, s2>>>(
      wh + WOFF_KV, wl + WOFF_KV, pfh, kv_b, (float*)nullptr, kvh, kvl, 2*DIM, DIM, HWP);

  // -- main: q_local conv
  conv1x1_hf_kernel<<<dim3((HWX + 127)/128, DIM/128, BATCH), 256, CV_SMEM>>>(
      wh + WOFF_Q, wl + WOFF_Q, xh, q_b, (float*)nullptr, qh, (fp16*)nullptr, DIM, DIM, HWX);

  // join
  cudaEventRecord(eJoin, s2);
  cudaStreamWaitEvent(0, eJoin, 0);

  // 6. attention -> gf16
  attn7_kernel<<<BATCH*HEADS*7, 128, A6_BYTES>>>(qh, kvh, kvl, gf16);
  // 7. local mixer + gating -> mh
  gate_y4_kernel<<<(BATCH*DIM*14*WW + 255)/256, 256>>>(qh, loc_w, loc_b, gf16, mh);
  // 8. out = conv1x1(mixbuf) -> f32
  conv1x1_hf_kernel<<<dim3((HWX + 127)/128, DIM/128, BATCH), 256, CV_SMEM>>>(
      wh + WOFF_MIX, wl + WOFF_MIX, mh, mix_b, out, (fp16*)nullptr, (fp16*)nullptr, DIM, DIM, HWX);
}